// round 5
// baseline (speedup 1.0000x reference)
#include <cuda_runtime.h>
#include <cuda_bf16.h>
#include <cstdint>

#define BATCH 2
#define T 2048
#define D 1024
#define H 16
#define HD 64

// ---------------- scratch (allocation-free) ----------------
__device__ __nv_bfloat16 g_qh[BATCH*T*D], g_ql[BATCH*T*D];
__device__ __nv_bfloat16 g_kh[BATCH*T*D], g_kl[BATCH*T*D];
__device__ __nv_bfloat16 g_vh[BATCH*T*D], g_vl[BATCH*T*D];
__device__ __nv_bfloat16 g_Wqh[D*D], g_Wql[D*D];
__device__ __nv_bfloat16 g_Wkh[D*D], g_Wkl[D*D];
__device__ __nv_bfloat16 g_Wvh[D*D], g_Wvl[D*D];
__device__ __nv_bfloat16 g_Woh[D*D], g_Wol[D*D];
__device__ __nv_bfloat16 g_Oh[BATCH*T*D], g_Ol[BATCH*T*D];
__device__ float g_Q[BATCH*H*T*HD];
__device__ float g_K[BATCH*H*T*HD];
__device__ float g_V[BATCH*H*T*HD];

// ---------------- PTX helpers (family-portable: sm_80+ features only) ------
__device__ __forceinline__ uint32_t smem_u32(const void* p) {
    uint32_t a;
    asm("{ .reg .u64 t; cvta.to.shared.u64 t, %1; cvt.u32.u64 %0, t; }" : "=r"(a) : "l"(p));
    return a;
}
__device__ __forceinline__ void cp16(uint32_t s, const void* g) {
    asm volatile("cp.async.cg.shared.global [%0], [%1], 16;" :: "r"(s), "l"(g));
}
__device__ __forceinline__ void cp_commit() {
    asm volatile("cp.async.commit_group;" ::: "memory");
}
template<int N> __device__ __forceinline__ void cp_wait() {
    asm volatile("cp.async.wait_group %0;" :: "n"(N) : "memory");
}
__device__ __forceinline__ void ldsm4(uint32_t* r, uint32_t addr) {
    asm volatile("ldmatrix.sync.aligned.m8n8.x4.shared.b16 {%0,%1,%2,%3}, [%4];"
                 : "=r"(r[0]), "=r"(r[1]), "=r"(r[2]), "=r"(r[3]) : "r"(addr));
}
__device__ __forceinline__ void mma16816(float* c, const uint32_t* a, const uint32_t* b) {
    asm volatile(
        "mma.sync.aligned.m16n8k16.row.col.f32.bf16.bf16.f32 "
        "{%0,%1,%2,%3}, {%4,%5,%6,%7}, {%8,%9}, {%0,%1,%2,%3};"
        : "+f"(c[0]), "+f"(c[1]), "+f"(c[2]), "+f"(c[3])
        : "r"(a[0]), "r"(a[1]), "r"(a[2]), "r"(a[3]), "r"(b[0]), "r"(b[1]));
}

// ---------------- GEMM geometry ----------------
#define BM 128
#define BN 128
#define BK 32
#define ROWB 80                    // padded smem row: 32 bf16 + 8 pad = 80B (16B aligned, conflict-free ldmatrix)
#define TILE_SMEM (128 * ROWB)     // 10240 B per operand tile
#define BUF_BYTES (4 * TILE_SMEM)  // Ah, Al, Bh, Bl
#define GEMM_SMEM (2 * BUF_BYTES)  // double buffered: 81920 B

// ---------------- split convert: fp32 -> (hi, lo) bf16 ----------------
__global__ __launch_bounds__(256) void cvt_kernel(const float* __restrict__ src, int tag) {
    __nv_bfloat16 *hi, *lo;
    switch (tag) {
        case 0: hi = g_qh;  lo = g_ql;  break;
        case 1: hi = g_kh;  lo = g_kl;  break;
        case 2: hi = g_vh;  lo = g_vl;  break;
        case 3: hi = g_Wqh; lo = g_Wql; break;
        case 4: hi = g_Wkh; lo = g_Wkl; break;
        case 5: hi = g_Wvh; lo = g_Wvl; break;
        default: hi = g_Woh; lo = g_Wol; break;
    }
    int i = (blockIdx.x * 256 + threadIdx.x) * 4;
    float4 v = *(const float4*)(src + i);
    float vv[4] = {v.x, v.y, v.z, v.w};
    __nv_bfloat16 h[4], l[4];
    #pragma unroll
    for (int j = 0; j < 4; j++) {
        h[j] = __float2bfloat16(vv[j]);
        l[j] = __float2bfloat16(vv[j] - __bfloat162float(h[j]));
    }
    *(__nv_bfloat162*)(hi + i)     = __nv_bfloat162(h[0], h[1]);
    *(__nv_bfloat162*)(hi + i + 2) = __nv_bfloat162(h[2], h[3]);
    *(__nv_bfloat162*)(lo + i)     = __nv_bfloat162(l[0], l[1]);
    *(__nv_bfloat162*)(lo + i + 2) = __nv_bfloat162(l[2], l[3]);
}

// ---------------- shared HMMA mainloop ----------------
// C(128x128 fp32, register-tiled) = A @ B^T via split-bf16 (3 MMAs / k-step)
__device__ __forceinline__ void hmma_issue(
    uint32_t sb, int buf,
    const __nv_bfloat16* __restrict__ Ah, const __nv_bfloat16* __restrict__ Al,
    const __nv_bfloat16* __restrict__ Bh, const __nv_bfloat16* __restrict__ Bl,
    int row0, int col0, int kc)
{
    int tid = threadIdx.x;
    const __nv_bfloat16* srcs[4] = {Ah, Al, Bh, Bl};
    int bases[4] = {row0, row0, col0, col0};
    #pragma unroll
    for (int t = 0; t < 4; t++) {
        #pragma unroll
        for (int j = 0; j < 2; j++) {
            int idx = tid + j * 256;         // 0..511
            int row = idx >> 2, g = idx & 3;
            cp16(sb + buf * BUF_BYTES + t * TILE_SMEM + row * ROWB + g * 16,
                 srcs[t] + (size_t)(bases[t] + row) * D + kc + g * 8);
        }
    }
}

__device__ __forceinline__ void hmma_gemm(
    uint32_t sb,
    const __nv_bfloat16* __restrict__ Ah, const __nv_bfloat16* __restrict__ Al,
    const __nv_bfloat16* __restrict__ Bh, const __nv_bfloat16* __restrict__ Bl,
    int row0, int col0, float c[4][4][4])
{
    int tid = threadIdx.x;
    int lane = tid & 31, wid = tid >> 5;
    int m0 = (wid >> 2) * 64, n0 = (wid & 3) * 32;
    int mt = lane >> 3, lr = lane & 7;
    uint32_t aoff = (uint32_t)((m0 + (mt & 1) * 8 + lr) * ROWB + ((mt >> 1) * 8) * 2);
    uint32_t boff = (uint32_t)((n0 + (mt >> 1) * 8 + lr) * ROWB + ((mt & 1) * 8) * 2);

    #pragma unroll
    for (int i = 0; i < 4; i++)
        #pragma unroll
        for (int j = 0; j < 4; j++)
            #pragma unroll
            for (int f = 0; f < 4; f++) c[i][j][f] = 0.f;

    hmma_issue(sb, 0, Ah, Al, Bh, Bl, row0, col0, 0);  cp_commit();
    hmma_issue(sb, 1, Ah, Al, Bh, Bl, row0, col0, 32); cp_commit();

    #pragma unroll 1
    for (int cch = 0; cch < 32; cch++) {
        if (cch < 31) cp_wait<1>(); else cp_wait<0>();
        __syncthreads();
        uint32_t bufb = sb + (cch & 1) * BUF_BYTES;

        #pragma unroll
        for (int kk = 0; kk < 32; kk += 16) {
            uint32_t bh[4][2], bl[4][2];
            #pragma unroll
            for (int jp = 0; jp < 2; jp++) {
                uint32_t r[4];
                ldsm4(r, bufb + 2 * TILE_SMEM + boff + jp * 16 * ROWB + kk * 2);
                bh[2*jp][0] = r[0]; bh[2*jp][1] = r[1];
                bh[2*jp+1][0] = r[2]; bh[2*jp+1][1] = r[3];
                ldsm4(r, bufb + 3 * TILE_SMEM + boff + jp * 16 * ROWB + kk * 2);
                bl[2*jp][0] = r[0]; bl[2*jp][1] = r[1];
                bl[2*jp+1][0] = r[2]; bl[2*jp+1][1] = r[3];
            }
            #pragma unroll
            for (int i = 0; i < 4; i++) {
                uint32_t ah[4], al[4];
                ldsm4(ah, bufb + 0 * TILE_SMEM + aoff + i * 16 * ROWB + kk * 2);
                ldsm4(al, bufb + 1 * TILE_SMEM + aoff + i * 16 * ROWB + kk * 2);
                #pragma unroll
                for (int j = 0; j < 4; j++) {
                    mma16816(c[i][j], ah, bh[j]);
                    mma16816(c[i][j], ah, bl[j]);
                    mma16816(c[i][j], al, bh[j]);
                }
            }
        }
        __syncthreads();
        if (cch + 2 < 32) { hmma_issue(sb, cch & 1, Ah, Al, Bh, Bl, row0, col0, (cch + 2) * 32); cp_commit(); }
    }
}

// ---------------- projection GEMM (q/k/v via blockIdx.z), head-split scatter -
__global__ __launch_bounds__(256, 2)
void proj_hmma() {
    extern __shared__ char sm[];
    uint32_t sb = smem_u32(sm);
    const __nv_bfloat16 *Ah, *Al, *Bh, *Bl; float* out;
    if (blockIdx.z == 0)      { Ah = g_qh; Al = g_ql; Bh = g_Wqh; Bl = g_Wql; out = g_Q; }
    else if (blockIdx.z == 1) { Ah = g_kh; Al = g_kl; Bh = g_Wkh; Bl = g_Wkl; out = g_K; }
    else                      { Ah = g_vh; Al = g_vl; Bh = g_Wvh; Bl = g_Wvl; out = g_V; }
    int row0 = blockIdx.y * BM, col0 = blockIdx.x * BN;

    float c[4][4][4];
    hmma_gemm(sb, Ah, Al, Bh, Bl, row0, col0, c);

    int lane = threadIdx.x & 31, wid = threadIdx.x >> 5;
    int m0 = (wid >> 2) * 64, n0 = (wid & 3) * 32;
    int trow = lane >> 2, tcol = (lane & 3) * 2;
    #pragma unroll
    for (int i = 0; i < 4; i++) {
        #pragma unroll
        for (int half = 0; half < 2; half++) {
            int row = row0 + m0 + 16 * i + trow + half * 8;
            int bb = row >> 11, tt = row & 2047;
            #pragma unroll
            for (int j = 0; j < 4; j++) {
                int col = col0 + n0 + 8 * j + tcol;
                int h = col >> 6, d = col & 63;
                float* op = out + (((size_t)bb * H + h) * T + tt) * HD + d;
                op[0] = c[i][j][half * 2 + 0];
                op[1] = c[i][j][half * 2 + 1];
            }
        }
    }
}

// ---------------- output projection GEMM + bias ----------------
__global__ __launch_bounds__(256, 2)
void out_hmma(const float* __restrict__ bo, float* __restrict__ dout) {
    extern __shared__ char sm[];
    uint32_t sb = smem_u32(sm);
    int row0 = blockIdx.y * BM, col0 = blockIdx.x * BN;

    float c[4][4][4];
    hmma_gemm(sb, g_Oh, g_Ol, g_Woh, g_Wol, row0, col0, c);

    int lane = threadIdx.x & 31, wid = threadIdx.x >> 5;
    int m0 = (wid >> 2) * 64, n0 = (wid & 3) * 32;
    int trow = lane >> 2, tcol = (lane & 3) * 2;
    #pragma unroll
    for (int i = 0; i < 4; i++) {
        #pragma unroll
        for (int half = 0; half < 2; half++) {
            int row = row0 + m0 + 16 * i + trow + half * 8;
            #pragma unroll
            for (int j = 0; j < 4; j++) {
                int col = col0 + n0 + 8 * j + tcol;
                float2 b2 = *(const float2*)(bo + col);
                float2 v2 = make_float2(c[i][j][half * 2 + 0] + b2.x,
                                        c[i][j][half * 2 + 1] + b2.y);
                *(float2*)(dout + (size_t)row * D + col) = v2;
            }
        }
    }
}

// ---------------------------------------------------------------------------
// Flash attention (fp32 SIMT) — epilogue emits bf16 hi/lo of O
// ---------------------------------------------------------------------------
__global__ __launch_bounds__(256) void attn_kernel()
{
    extern __shared__ float smem[];
    float* Qs = smem;          // [64][64]
    float* Ks = smem + 4096;   // [64][64] dim-major
    float* Vs = smem + 8192;   // [64][64]
    float* Ps = smem + 12288;  // [64][64]

    int bh = blockIdx.y;
    int qt0 = blockIdx.x * 64;
    const float* Qg = g_Q + (size_t)bh * T * HD + (size_t)qt0 * HD;
    const float* Kg = g_K + (size_t)bh * T * HD;
    const float* Vg = g_V + (size_t)bh * T * HD;

    int tid = threadIdx.x;
    int lane = tid & 31;
    int warp = tid >> 5;
    int r0 = warp * 8;

    for (int i = tid; i < 64 * 16; i += 256) {
        int r = i >> 4, c4 = (i & 15) * 4;
        *(float4*)(Qs + r*64 + c4) = *(const float4*)(Qg + r*64 + c4);
    }

    float m_i[8], l_i[8], o0[8], o1[8];
    #pragma unroll
    for (int r = 0; r < 8; r++) { m_i[r] = -1e30f; l_i[r] = 0.f; o0[r] = 0.f; o1[r] = 0.f; }

    for (int kc = 0; kc < T; kc += 64) {
        __syncthreads();
        for (int i = tid; i < 64 * 16; i += 256) {
            int r = i >> 4, c4 = (i & 15) * 4;
            float4 kv = *(const float4*)(Kg + (size_t)(kc + r)*64 + c4);
            Ks[(c4+0)*64 + r] = kv.x;
            Ks[(c4+1)*64 + r] = kv.y;
            Ks[(c4+2)*64 + r] = kv.z;
            Ks[(c4+3)*64 + r] = kv.w;
            *(float4*)(Vs + r*64 + c4) = *(const float4*)(Vg + (size_t)(kc + r)*64 + c4);
        }
        __syncthreads();

        float s0[8], s1[8];
        #pragma unroll
        for (int r = 0; r < 8; r++) { s0[r] = 0.f; s1[r] = 0.f; }
        #pragma unroll 4
        for (int k = 0; k < 64; k++) {
            float kv1 = Ks[k*64 + lane];
            float kv2 = Ks[k*64 + lane + 32];
            #pragma unroll
            for (int r = 0; r < 8; r++) {
                float qv = Qs[(r0 + r)*64 + k];
                s0[r] = fmaf(qv, kv1, s0[r]);
                s1[r] = fmaf(qv, kv2, s1[r]);
            }
        }

        #pragma unroll
        for (int r = 0; r < 8; r++) {
            float sa = s0[r] * 0.125f;
            float sb = s1[r] * 0.125f;
            float mx = fmaxf(sa, sb);
            #pragma unroll
            for (int off = 16; off; off >>= 1)
                mx = fmaxf(mx, __shfl_xor_sync(0xffffffffu, mx, off));
            float mnew = fmaxf(m_i[r], mx);
            float p0 = __expf(sa - mnew);
            float p1 = __expf(sb - mnew);
            float alpha = __expf(m_i[r] - mnew);
            float rs = p0 + p1;
            #pragma unroll
            for (int off = 16; off; off >>= 1)
                rs += __shfl_xor_sync(0xffffffffu, rs, off);
            l_i[r] = l_i[r] * alpha + rs;
            m_i[r] = mnew;
            o0[r] *= alpha;
            o1[r] *= alpha;
            Ps[(r0 + r)*64 + lane] = p0;
            Ps[(r0 + r)*64 + lane + 32] = p1;
        }
        __syncwarp();

        #pragma unroll 4
        for (int j = 0; j < 64; j++) {
            float v1 = Vs[j*64 + lane];
            float v2 = Vs[j*64 + lane + 32];
            #pragma unroll
            for (int r = 0; r < 8; r++) {
                float p = Ps[(r0 + r)*64 + j];
                o0[r] = fmaf(p, v1, o0[r]);
                o1[r] = fmaf(p, v2, o1[r]);
            }
        }
    }

    int b = bh >> 4, h = bh & 15;
    #pragma unroll
    for (int r = 0; r < 8; r++) {
        float inv = 1.0f / l_i[r];
        int t = qt0 + r0 + r;
        size_t base = ((size_t)b*T + t)*D + h*HD;
        float x0 = o0[r] * inv, x1 = o1[r] * inv;
        __nv_bfloat16 h0 = __float2bfloat16(x0);
        __nv_bfloat16 h1 = __float2bfloat16(x1);
        g_Oh[base + lane]      = h0;
        g_Oh[base + lane + 32] = h1;
        g_Ol[base + lane]      = __float2bfloat16(x0 - __bfloat162float(h0));
        g_Ol[base + lane + 32] = __float2bfloat16(x1 - __bfloat162float(h1));
    }
}

// ---------------------------------------------------------------------------
extern "C" void kernel_launch(void* const* d_in, const int* in_sizes, int n_in,
                              void* d_out, int out_size)
{
    const float* k  = (const float*)d_in[0];
    const float* q  = (const float*)d_in[1];
    const float* v  = (const float*)d_in[2];
    const float* Wk = (const float*)d_in[3];
    const float* Wq = (const float*)d_in[4];
    const float* Wv = (const float*)d_in[5];
    const float* Wo = (const float*)d_in[6];
    const float* bo = (const float*)d_in[7];
    float* out = (float*)d_out;

    cudaFuncSetAttribute(attn_kernel, cudaFuncAttributeMaxDynamicSharedMemorySize, 65536);
    cudaFuncSetAttribute(proj_hmma,   cudaFuncAttributeMaxDynamicSharedMemorySize, GEMM_SMEM);
    cudaFuncSetAttribute(out_hmma,    cudaFuncAttributeMaxDynamicSharedMemorySize, GEMM_SMEM);

    // 1) split inputs/weights into bf16 hi/lo
    cvt_kernel<<<(BATCH*T*D)/1024, 256>>>(q,  0);
    cvt_kernel<<<(BATCH*T*D)/1024, 256>>>(k,  1);
    cvt_kernel<<<(BATCH*T*D)/1024, 256>>>(v,  2);
    cvt_kernel<<<(D*D)/1024, 256>>>(Wq, 3);
    cvt_kernel<<<(D*D)/1024, 256>>>(Wk, 4);
    cvt_kernel<<<(D*D)/1024, 256>>>(Wv, 5);
    cvt_kernel<<<(D*D)/1024, 256>>>(Wo, 6);

    // 2) Q/K/V projections on tensor cores (split-bf16, fp32 accum)
    proj_hmma<<<dim3(D/BN, (BATCH*T)/BM, 3), 256, GEMM_SMEM>>>();

    // 3) flash attention (fp32), emits bf16 hi/lo of O
    attn_kernel<<<dim3(T/64, BATCH*H), 256, 65536>>>();

    // 4) output projection + bias on tensor cores
    out_hmma<<<dim3(D/BN, (BATCH*T)/BM), 256, GEMM_SMEM>>>(bo, out);
}

// round 7
// speedup vs baseline: 1.5004x; 1.5004x over previous
#include <cuda_runtime.h>
#include <cuda_bf16.h>
#include <cstdint>

#define BATCH 2
#define T 2048
#define D 1024
#define H 16
#define HD 64

// ---------------- scratch (allocation-free) ----------------
__device__ __nv_bfloat16 g_qh[BATCH*T*D], g_ql[BATCH*T*D];
__device__ __nv_bfloat16 g_kh[BATCH*T*D], g_kl[BATCH*T*D];
__device__ __nv_bfloat16 g_vh[BATCH*T*D], g_vl[BATCH*T*D];
__device__ __nv_bfloat16 g_Wqh[D*D], g_Wql[D*D];
__device__ __nv_bfloat16 g_Wkh[D*D], g_Wkl[D*D];
__device__ __nv_bfloat16 g_Wvh[D*D], g_Wvl[D*D];
__device__ __nv_bfloat16 g_Woh[D*D], g_Wol[D*D];
__device__ __nv_bfloat16 g_Oh[BATCH*T*D], g_Ol[BATCH*T*D];
__device__ float g_Q[BATCH*H*T*HD];
__device__ float g_K[BATCH*H*T*HD];
__device__ float g_V[BATCH*H*T*HD];

// ---------------- PTX helpers (family-portable: sm_80+ only) ----------------
__device__ __forceinline__ uint32_t smem_u32(const void* p) {
    uint32_t a;
    asm("{ .reg .u64 t; cvta.to.shared.u64 t, %1; cvt.u32.u64 %0, t; }" : "=r"(a) : "l"(p));
    return a;
}
__device__ __forceinline__ void cp16(uint32_t s, const void* g) {
    asm volatile("cp.async.cg.shared.global [%0], [%1], 16;" :: "r"(s), "l"(g));
}
__device__ __forceinline__ void cp_commit() {
    asm volatile("cp.async.commit_group;" ::: "memory");
}
template<int N> __device__ __forceinline__ void cp_wait() {
    asm volatile("cp.async.wait_group %0;" :: "n"(N) : "memory");
}
__device__ __forceinline__ void ldsm4(uint32_t* r, uint32_t addr) {
    asm volatile("ldmatrix.sync.aligned.m8n8.x4.shared.b16 {%0,%1,%2,%3}, [%4];"
                 : "=r"(r[0]), "=r"(r[1]), "=r"(r[2]), "=r"(r[3]) : "r"(addr));
}
__device__ __forceinline__ void mma16816(float* c, const uint32_t* a, const uint32_t* b) {
    asm volatile(
        "mma.sync.aligned.m16n8k16.row.col.f32.bf16.bf16.f32 "
        "{%0,%1,%2,%3}, {%4,%5,%6,%7}, {%8,%9}, {%0,%1,%2,%3};"
        : "+f"(c[0]), "+f"(c[1]), "+f"(c[2]), "+f"(c[3])
        : "r"(a[0]), "r"(a[1]), "r"(a[2]), "r"(a[3]), "r"(b[0]), "r"(b[1]));
}

// ---------------- GEMM geometry ----------------
#define BM 128
#define BN 128
#define BK 32
#define ROWB 80                    // 32 bf16 + 16B pad: 16B-aligned, conflict-free ldmatrix
#define TILE_SMEM (128 * ROWB)     // 10240 B per operand tile
#define BUF_BYTES (4 * TILE_SMEM)  // Ah, Al, Bh, Bl
#define GEMM_SMEM (2 * BUF_BYTES)  // double buffered: 81920 B
#define GTHREADS 512               // 16 warps, warp tile 32x32 -> 32 accum regs/thread

// ---------------- fused split convert: fp32 -> (hi, lo) bf16 ----------------
// 16384 blocks x 256 threads x 4 elems. Block ranges select the tensor.
__global__ __launch_bounds__(256) void cvt_all(
    const float* __restrict__ q, const float* __restrict__ k, const float* __restrict__ v,
    const float* __restrict__ Wq, const float* __restrict__ Wk,
    const float* __restrict__ Wv, const float* __restrict__ Wo)
{
    int b = blockIdx.x;
    const float* src; __nv_bfloat16 *hi, *lo; int lb;
    if (b < 4096)       { src = q;  hi = g_qh;  lo = g_ql;  lb = b; }
    else if (b < 8192)  { src = k;  hi = g_kh;  lo = g_kl;  lb = b - 4096; }
    else if (b < 12288) { src = v;  hi = g_vh;  lo = g_vl;  lb = b - 8192; }
    else if (b < 13312) { src = Wq; hi = g_Wqh; lo = g_Wql; lb = b - 12288; }
    else if (b < 14336) { src = Wk; hi = g_Wkh; lo = g_Wkl; lb = b - 13312; }
    else if (b < 15360) { src = Wv; hi = g_Wvh; lo = g_Wvl; lb = b - 14336; }
    else                { src = Wo; hi = g_Woh; lo = g_Wol; lb = b - 15360; }
    int i = lb * 1024 + threadIdx.x * 4;
    float4 vv4 = *(const float4*)(src + i);
    float vv[4] = {vv4.x, vv4.y, vv4.z, vv4.w};
    __nv_bfloat16 h[4], l[4];
    #pragma unroll
    for (int j = 0; j < 4; j++) {
        h[j] = __float2bfloat16(vv[j]);
        l[j] = __float2bfloat16(vv[j] - __bfloat162float(h[j]));
    }
    *(__nv_bfloat162*)(hi + i)     = __nv_bfloat162(h[0], h[1]);
    *(__nv_bfloat162*)(hi + i + 2) = __nv_bfloat162(h[2], h[3]);
    *(__nv_bfloat162*)(lo + i)     = __nv_bfloat162(l[0], l[1]);
    *(__nv_bfloat162*)(lo + i + 2) = __nv_bfloat162(l[2], l[3]);
}

// ---------------- shared HMMA mainloop ----------------
__device__ __forceinline__ void hmma_issue(
    uint32_t sb, int buf,
    const __nv_bfloat16* __restrict__ Ah, const __nv_bfloat16* __restrict__ Al,
    const __nv_bfloat16* __restrict__ Bh, const __nv_bfloat16* __restrict__ Bl,
    int row0, int col0, int kc)
{
    int tid = threadIdx.x;                     // 0..511
    int row = tid >> 2, g = tid & 3;           // 128 rows x 4 16B segs
    const __nv_bfloat16* srcs[4] = {Ah, Al, Bh, Bl};
    int bases[4] = {row0, row0, col0, col0};
    #pragma unroll
    for (int t = 0; t < 4; t++) {
        cp16(sb + buf * BUF_BYTES + t * TILE_SMEM + row * ROWB + g * 16,
             srcs[t] + (size_t)(bases[t] + row) * D + kc + g * 8);
    }
}

// C(128x128 fp32) = A @ B^T via split-bf16 (AhBh + AhBl + AlBh), warp tile 32x32
__device__ __forceinline__ void hmma_gemm(
    uint32_t sb,
    const __nv_bfloat16* __restrict__ Ah, const __nv_bfloat16* __restrict__ Al,
    const __nv_bfloat16* __restrict__ Bh, const __nv_bfloat16* __restrict__ Bl,
    int row0, int col0, float c[2][4][4])
{
    int tid = threadIdx.x;
    int lane = tid & 31, wid = tid >> 5;
    int m0 = (wid >> 2) * 32, n0 = (wid & 3) * 32;
    int mt = lane >> 3, lr = lane & 7;
    uint32_t aoff = (uint32_t)((m0 + (mt & 1) * 8 + lr) * ROWB + ((mt >> 1) * 8) * 2);
    uint32_t boff = (uint32_t)((n0 + (mt >> 1) * 8 + lr) * ROWB + ((mt & 1) * 8) * 2);

    #pragma unroll
    for (int i = 0; i < 2; i++)
        #pragma unroll
        for (int j = 0; j < 4; j++)
            #pragma unroll
            for (int f = 0; f < 4; f++) c[i][j][f] = 0.f;

    hmma_issue(sb, 0, Ah, Al, Bh, Bl, row0, col0, 0);  cp_commit();
    hmma_issue(sb, 1, Ah, Al, Bh, Bl, row0, col0, 32); cp_commit();

    #pragma unroll 1
    for (int cch = 0; cch < 32; cch++) {
        if (cch < 31) cp_wait<1>(); else cp_wait<0>();
        __syncthreads();
        uint32_t bufb = sb + (cch & 1) * BUF_BYTES;

        #pragma unroll
        for (int kk = 0; kk < 32; kk += 16) {
            uint32_t bh[4][2], bl[4][2];
            #pragma unroll
            for (int jp = 0; jp < 2; jp++) {
                uint32_t r[4];
                ldsm4(r, bufb + 2 * TILE_SMEM + boff + jp * 16 * ROWB + kk * 2);
                bh[2*jp][0] = r[0]; bh[2*jp][1] = r[1];
                bh[2*jp+1][0] = r[2]; bh[2*jp+1][1] = r[3];
                ldsm4(r, bufb + 3 * TILE_SMEM + boff + jp * 16 * ROWB + kk * 2);
                bl[2*jp][0] = r[0]; bl[2*jp][1] = r[1];
                bl[2*jp+1][0] = r[2]; bl[2*jp+1][1] = r[3];
            }
            #pragma unroll
            for (int i = 0; i < 2; i++) {
                uint32_t ah[4], al[4];
                ldsm4(ah, bufb + 0 * TILE_SMEM + aoff + i * 16 * ROWB + kk * 2);
                ldsm4(al, bufb + 1 * TILE_SMEM + aoff + i * 16 * ROWB + kk * 2);
                #pragma unroll
                for (int j = 0; j < 4; j++) {
                    mma16816(c[i][j], ah, bh[j]);
                    mma16816(c[i][j], ah, bl[j]);
                    mma16816(c[i][j], al, bh[j]);
                }
            }
        }
        __syncthreads();
        if (cch + 2 < 32) { hmma_issue(sb, cch & 1, Ah, Al, Bh, Bl, row0, col0, (cch + 2) * 32); cp_commit(); }
    }
}

// ---------------- projection GEMM (q/k/v via blockIdx.z), head-split scatter -
__global__ __launch_bounds__(GTHREADS, 1)
void proj_hmma() {
    extern __shared__ char sm[];
    uint32_t sb = smem_u32(sm);
    const __nv_bfloat16 *Ah, *Al, *Bh, *Bl; float* out;
    if (blockIdx.z == 0)      { Ah = g_qh; Al = g_ql; Bh = g_Wqh; Bl = g_Wql; out = g_Q; }
    else if (blockIdx.z == 1) { Ah = g_kh; Al = g_kl; Bh = g_Wkh; Bl = g_Wkl; out = g_K; }
    else                      { Ah = g_vh; Al = g_vl; Bh = g_Wvh; Bl = g_Wvl; out = g_V; }
    int row0 = blockIdx.y * BM, col0 = blockIdx.x * BN;

    float c[2][4][4];
    hmma_gemm(sb, Ah, Al, Bh, Bl, row0, col0, c);

    int lane = threadIdx.x & 31, wid = threadIdx.x >> 5;
    int m0 = (wid >> 2) * 32, n0 = (wid & 3) * 32;
    int trow = lane >> 2, tcol = (lane & 3) * 2;
    #pragma unroll
    for (int i = 0; i < 2; i++) {
        #pragma unroll
        for (int half = 0; half < 2; half++) {
            int row = row0 + m0 + 16 * i + trow + half * 8;
            int bb = row >> 11, tt = row & 2047;
            #pragma unroll
            for (int j = 0; j < 4; j++) {
                int col = col0 + n0 + 8 * j + tcol;
                int h = col >> 6, d = col & 63;
                float* op = out + (((size_t)bb * H + h) * T + tt) * HD + d;
                op[0] = c[i][j][half * 2 + 0];
                op[1] = c[i][j][half * 2 + 1];
            }
        }
    }
}

// ---------------- output projection GEMM + bias ----------------
__global__ __launch_bounds__(GTHREADS, 1)
void out_hmma(const float* __restrict__ bo, float* __restrict__ dout) {
    extern __shared__ char sm[];
    uint32_t sb = smem_u32(sm);
    int row0 = blockIdx.y * BM, col0 = blockIdx.x * BN;

    float c[2][4][4];
    hmma_gemm(sb, g_Oh, g_Ol, g_Woh, g_Wol, row0, col0, c);

    int lane = threadIdx.x & 31, wid = threadIdx.x >> 5;
    int m0 = (wid >> 2) * 32, n0 = (wid & 3) * 32;
    int trow = lane >> 2, tcol = (lane & 3) * 2;
    #pragma unroll
    for (int i = 0; i < 2; i++) {
        #pragma unroll
        for (int half = 0; half < 2; half++) {
            int row = row0 + m0 + 16 * i + trow + half * 8;
            #pragma unroll
            for (int j = 0; j < 4; j++) {
                int col = col0 + n0 + 8 * j + tcol;
                float2 b2 = *(const float2*)(bo + col);
                float2 v2 = make_float2(c[i][j][half * 2 + 0] + b2.x,
                                        c[i][j][half * 2 + 1] + b2.y);
                *(float2*)(dout + (size_t)row * D + col) = v2;
            }
        }
    }
}

// ---------------------------------------------------------------------------
// Flash attention (fp32 SIMT, unchanged) — epilogue emits bf16 hi/lo of O
// ---------------------------------------------------------------------------
__global__ __launch_bounds__(256) void attn_kernel()
{
    extern __shared__ float smem[];
    float* Qs = smem;          // [64][64]
    float* Ks = smem + 4096;   // [64][64] dim-major
    float* Vs = smem + 8192;   // [64][64]
    float* Ps = smem + 12288;  // [64][64]

    int bh = blockIdx.y;
    int qt0 = blockIdx.x * 64;
    const float* Qg = g_Q + (size_t)bh * T * HD + (size_t)qt0 * HD;
    const float* Kg = g_K + (size_t)bh * T * HD;
    const float* Vg = g_V + (size_t)bh * T * HD;

    int tid = threadIdx.x;
    int lane = tid & 31;
    int warp = tid >> 5;
    int r0 = warp * 8;

    for (int i = tid; i < 64 * 16; i += 256) {
        int r = i >> 4, c4 = (i & 15) * 4;
        *(float4*)(Qs + r*64 + c4) = *(const float4*)(Qg + r*64 + c4);
    }

    float m_i[8], l_i[8], o0[8], o1[8];
    #pragma unroll
    for (int r = 0; r < 8; r++) { m_i[r] = -1e30f; l_i[r] = 0.f; o0[r] = 0.f; o1[r] = 0.f; }

    for (int kc = 0; kc < T; kc += 64) {
        __syncthreads();
        for (int i = tid; i < 64 * 16; i += 256) {
            int r = i >> 4, c4 = (i & 15) * 4;
            float4 kv = *(const float4*)(Kg + (size_t)(kc + r)*64 + c4);
            Ks[(c4+0)*64 + r] = kv.x;
            Ks[(c4+1)*64 + r] = kv.y;
            Ks[(c4+2)*64 + r] = kv.z;
            Ks[(c4+3)*64 + r] = kv.w;
            *(float4*)(Vs + r*64 + c4) = *(const float4*)(Vg + (size_t)(kc + r)*64 + c4);
        }
        __syncthreads();

        float s0[8], s1[8];
        #pragma unroll
        for (int r = 0; r < 8; r++) { s0[r] = 0.f; s1[r] = 0.f; }
        #pragma unroll 4
        for (int k = 0; k < 64; k++) {
            float kv1 = Ks[k*64 + lane];
            float kv2 = Ks[k*64 + lane + 32];
            #pragma unroll
            for (int r = 0; r < 8; r++) {
                float qv = Qs[(r0 + r)*64 + k];
                s0[r] = fmaf(qv, kv1, s0[r]);
                s1[r] = fmaf(qv, kv2, s1[r]);
            }
        }

        #pragma unroll
        for (int r = 0; r < 8; r++) {
            float sa = s0[r] * 0.125f;
            float sb = s1[r] * 0.125f;
            float mx = fmaxf(sa, sb);
            #pragma unroll
            for (int off = 16; off; off >>= 1)
                mx = fmaxf(mx, __shfl_xor_sync(0xffffffffu, mx, off));
            float mnew = fmaxf(m_i[r], mx);
            float p0 = __expf(sa - mnew);
            float p1 = __expf(sb - mnew);
            float alpha = __expf(m_i[r] - mnew);
            float rs = p0 + p1;
            #pragma unroll
            for (int off = 16; off; off >>= 1)
                rs += __shfl_xor_sync(0xffffffffu, rs, off);
            l_i[r] = l_i[r] * alpha + rs;
            m_i[r] = mnew;
            o0[r] *= alpha;
            o1[r] *= alpha;
            Ps[(r0 + r)*64 + lane] = p0;
            Ps[(r0 + r)*64 + lane + 32] = p1;
        }
        __syncwarp();

        #pragma unroll 4
        for (int j = 0; j < 64; j++) {
            float v1 = Vs[j*64 + lane];
            float v2 = Vs[j*64 + lane + 32];
            #pragma unroll
            for (int r = 0; r < 8; r++) {
                float p = Ps[(r0 + r)*64 + j];
                o0[r] = fmaf(p, v1, o0[r]);
                o1[r] = fmaf(p, v2, o1[r]);
            }
        }
    }

    int b = bh >> 4, h = bh & 15;
    #pragma unroll
    for (int r = 0; r < 8; r++) {
        float inv = 1.0f / l_i[r];
        int t = qt0 + r0 + r;
        size_t base = ((size_t)b*T + t)*D + h*HD;
        float x0 = o0[r] * inv, x1 = o1[r] * inv;
        __nv_bfloat16 h0 = __float2bfloat16(x0);
        __nv_bfloat16 h1 = __float2bfloat16(x1);
        g_Oh[base + lane]      = h0;
        g_Oh[base + lane + 32] = h1;
        g_Ol[base + lane]      = __float2bfloat16(x0 - __bfloat162float(h0));
        g_Ol[base + lane + 32] = __float2bfloat16(x1 - __bfloat162float(h1));
    }
}

// ---------------------------------------------------------------------------
extern "C" void kernel_launch(void* const* d_in, const int* in_sizes, int n_in,
                              void* d_out, int out_size)
{
    const float* k  = (const float*)d_in[0];
    const float* q  = (const float*)d_in[1];
    const float* v  = (const float*)d_in[2];
    const float* Wk = (const float*)d_in[3];
    const float* Wq = (const float*)d_in[4];
    const float* Wv = (const float*)d_in[5];
    const float* Wo = (const float*)d_in[6];
    const float* bo = (const float*)d_in[7];
    float* out = (float*)d_out;

    cudaFuncSetAttribute(attn_kernel, cudaFuncAttributeMaxDynamicSharedMemorySize, 65536);
    cudaFuncSetAttribute(proj_hmma,   cudaFuncAttributeMaxDynamicSharedMemorySize, GEMM_SMEM);
    cudaFuncSetAttribute(out_hmma,    cudaFuncAttributeMaxDynamicSharedMemorySize, GEMM_SMEM);

    // 1) split inputs/weights into bf16 hi/lo (single fused launch)
    cvt_all<<<16384, 256>>>(q, k, v, Wq, Wk, Wv, Wo);

    // 2) Q/K/V projections on tensor cores (split-bf16, fp32 accum)
    proj_hmma<<<dim3(D/BN, (BATCH*T)/BM, 3), GTHREADS, GEMM_SMEM>>>();

    // 3) flash attention (fp32), emits bf16 hi/lo of O
    attn_kernel<<<dim3(T/64, BATCH*H), 256, 65536>>>();

    // 4) output projection + bias on tensor cores
    out_hmma<<<dim3(D/BN, (BATCH*T)/BM), GTHREADS, GEMM_SMEM>>>(bo, out);
}

// round 11
// speedup vs baseline: 3.4090x; 2.2721x over previous
#include <cuda_runtime.h>
#include <cuda_bf16.h>
#include <cstdint>

#define BATCH 2
#define T 2048
#define D 1024
#define H 16
#define HD 64

// ---------------- scratch (allocation-free) ----------------
// split-bf16 inputs/weights for projections
__device__ __nv_bfloat16 g_qh[BATCH*T*D], g_ql[BATCH*T*D];
__device__ __nv_bfloat16 g_kh[BATCH*T*D], g_kl[BATCH*T*D];
__device__ __nv_bfloat16 g_vh[BATCH*T*D], g_vl[BATCH*T*D];
__device__ __nv_bfloat16 g_Wqh[D*D], g_Wql[D*D];
__device__ __nv_bfloat16 g_Wkh[D*D], g_Wkl[D*D];
__device__ __nv_bfloat16 g_Wvh[D*D], g_Wvl[D*D];
__device__ __nv_bfloat16 g_Woh[D*D], g_Wol[D*D];
// projected Q/K (split, [bh][t][n]) and V (split, TRANSPOSED [bh][n][t])
__device__ __nv_bfloat16 g_aQh[BATCH*H*T*HD], g_aQl[BATCH*H*T*HD];
__device__ __nv_bfloat16 g_aKh[BATCH*H*T*HD], g_aKl[BATCH*H*T*HD];
__device__ __nv_bfloat16 g_aVh[BATCH*H*T*HD], g_aVl[BATCH*H*T*HD];
// attention output (split, [b][t][h*64+d])
__device__ __nv_bfloat16 g_Oh[BATCH*T*D], g_Ol[BATCH*T*D];

// ---------------- PTX helpers (family-portable: sm_80+ only) ----------------
__device__ __forceinline__ uint32_t smem_u32(const void* p) {
    uint32_t a;
    asm("{ .reg .u64 t; cvta.to.shared.u64 t, %1; cvt.u32.u64 %0, t; }" : "=r"(a) : "l"(p));
    return a;
}
__device__ __forceinline__ void cp16(uint32_t s, const void* g) {
    asm volatile("cp.async.cg.shared.global [%0], [%1], 16;" :: "r"(s), "l"(g));
}
__device__ __forceinline__ void cp_commit() {
    asm volatile("cp.async.commit_group;" ::: "memory");
}
template<int N> __device__ __forceinline__ void cp_wait() {
    asm volatile("cp.async.wait_group %0;" :: "n"(N) : "memory");
}
__device__ __forceinline__ void ldsm4(uint32_t* r, uint32_t addr) {
    asm volatile("ldmatrix.sync.aligned.m8n8.x4.shared.b16 {%0,%1,%2,%3}, [%4];"
                 : "=r"(r[0]), "=r"(r[1]), "=r"(r[2]), "=r"(r[3]) : "r"(addr));
}
__device__ __forceinline__ void mma16816(float* c, const uint32_t* a, const uint32_t* b) {
    asm volatile(
        "mma.sync.aligned.m16n8k16.row.col.f32.bf16.bf16.f32 "
        "{%0,%1,%2,%3}, {%4,%5,%6,%7}, {%8,%9}, {%0,%1,%2,%3};"
        : "+f"(c[0]), "+f"(c[1]), "+f"(c[2]), "+f"(c[3])
        : "r"(a[0]), "r"(a[1]), "r"(a[2]), "r"(a[3]), "r"(b[0]), "r"(b[1]));
}
__device__ __forceinline__ uint32_t pack_hilo(__nv_bfloat16 lo, __nv_bfloat16 hi) {
    __nv_bfloat162 t(lo, hi);
    return *(uint32_t*)&t;
}

// ---------------- GEMM geometry ----------------
#define BM 128
#define BN 128
#define ROWB 80                    // 32 bf16 + 16B pad
#define TILE_SMEM (128 * ROWB)
#define BUF_BYTES (4 * TILE_SMEM)
#define GEMM_SMEM (2 * BUF_BYTES)  // 81920 B
#define GTHREADS 512

// ---------------- fused split convert: fp32 -> (hi, lo) bf16 ----------------
__global__ __launch_bounds__(256) void cvt_all(
    const float* __restrict__ q, const float* __restrict__ k, const float* __restrict__ v,
    const float* __restrict__ Wq, const float* __restrict__ Wk,
    const float* __restrict__ Wv, const float* __restrict__ Wo)
{
    int b = blockIdx.x;
    const float* src; __nv_bfloat16 *hi, *lo; int lb;
    if (b < 4096)       { src = q;  hi = g_qh;  lo = g_ql;  lb = b; }
    else if (b < 8192)  { src = k;  hi = g_kh;  lo = g_kl;  lb = b - 4096; }
    else if (b < 12288) { src = v;  hi = g_vh;  lo = g_vl;  lb = b - 8192; }
    else if (b < 13312) { src = Wq; hi = g_Wqh; lo = g_Wql; lb = b - 12288; }
    else if (b < 14336) { src = Wk; hi = g_Wkh; lo = g_Wkl; lb = b - 13312; }
    else if (b < 15360) { src = Wv; hi = g_Wvh; lo = g_Wvl; lb = b - 14336; }
    else                { src = Wo; hi = g_Woh; lo = g_Wol; lb = b - 15360; }
    int i = lb * 1024 + threadIdx.x * 4;
    float4 vv4 = *(const float4*)(src + i);
    float vv[4] = {vv4.x, vv4.y, vv4.z, vv4.w};
    __nv_bfloat16 h[4], l[4];
    #pragma unroll
    for (int j = 0; j < 4; j++) {
        h[j] = __float2bfloat16(vv[j]);
        l[j] = __float2bfloat16(vv[j] - __bfloat162float(h[j]));
    }
    *(__nv_bfloat162*)(hi + i)     = __nv_bfloat162(h[0], h[1]);
    *(__nv_bfloat162*)(hi + i + 2) = __nv_bfloat162(h[2], h[3]);
    *(__nv_bfloat162*)(lo + i)     = __nv_bfloat162(l[0], l[1]);
    *(__nv_bfloat162*)(lo + i + 2) = __nv_bfloat162(l[2], l[3]);
}

// ---------------- shared HMMA mainloop (128x128, split-bf16) ----------------
__device__ __forceinline__ void hmma_issue(
    uint32_t sb, int buf,
    const __nv_bfloat16* __restrict__ Ah, const __nv_bfloat16* __restrict__ Al,
    const __nv_bfloat16* __restrict__ Bh, const __nv_bfloat16* __restrict__ Bl,
    int row0, int col0, int kc)
{
    int tid = threadIdx.x;
    int row = tid >> 2, g = tid & 3;
    const __nv_bfloat16* srcs[4] = {Ah, Al, Bh, Bl};
    int bases[4] = {row0, row0, col0, col0};
    #pragma unroll
    for (int t = 0; t < 4; t++) {
        cp16(sb + buf * BUF_BYTES + t * TILE_SMEM + row * ROWB + g * 16,
             srcs[t] + (size_t)(bases[t] + row) * D + kc + g * 8);
    }
}

__device__ __forceinline__ void hmma_gemm(
    uint32_t sb,
    const __nv_bfloat16* __restrict__ Ah, const __nv_bfloat16* __restrict__ Al,
    const __nv_bfloat16* __restrict__ Bh, const __nv_bfloat16* __restrict__ Bl,
    int row0, int col0, float c[2][4][4])
{
    int tid = threadIdx.x;
    int lane = tid & 31, wid = tid >> 5;
    int m0 = (wid >> 2) * 32, n0 = (wid & 3) * 32;
    int mt = lane >> 3, lr = lane & 7;
    uint32_t aoff = (uint32_t)((m0 + (mt & 1) * 8 + lr) * ROWB + ((mt >> 1) * 8) * 2);
    uint32_t boff = (uint32_t)((n0 + (mt >> 1) * 8 + lr) * ROWB + ((mt & 1) * 8) * 2);

    #pragma unroll
    for (int i = 0; i < 2; i++)
        #pragma unroll
        for (int j = 0; j < 4; j++)
            #pragma unroll
            for (int f = 0; f < 4; f++) c[i][j][f] = 0.f;

    hmma_issue(sb, 0, Ah, Al, Bh, Bl, row0, col0, 0);  cp_commit();
    hmma_issue(sb, 1, Ah, Al, Bh, Bl, row0, col0, 32); cp_commit();

    #pragma unroll 1
    for (int cch = 0; cch < 32; cch++) {
        if (cch < 31) cp_wait<1>(); else cp_wait<0>();
        __syncthreads();
        uint32_t bufb = sb + (cch & 1) * BUF_BYTES;

        #pragma unroll
        for (int kk = 0; kk < 32; kk += 16) {
            uint32_t bh[4][2], bl[4][2];
            #pragma unroll
            for (int jp = 0; jp < 2; jp++) {
                uint32_t r[4];
                ldsm4(r, bufb + 2 * TILE_SMEM + boff + jp * 16 * ROWB + kk * 2);
                bh[2*jp][0] = r[0]; bh[2*jp][1] = r[1];
                bh[2*jp+1][0] = r[2]; bh[2*jp+1][1] = r[3];
                ldsm4(r, bufb + 3 * TILE_SMEM + boff + jp * 16 * ROWB + kk * 2);
                bl[2*jp][0] = r[0]; bl[2*jp][1] = r[1];
                bl[2*jp+1][0] = r[2]; bl[2*jp+1][1] = r[3];
            }
            #pragma unroll
            for (int i = 0; i < 2; i++) {
                uint32_t ah[4], al[4];
                ldsm4(ah, bufb + 0 * TILE_SMEM + aoff + i * 16 * ROWB + kk * 2);
                ldsm4(al, bufb + 1 * TILE_SMEM + aoff + i * 16 * ROWB + kk * 2);
                #pragma unroll
                for (int j = 0; j < 4; j++) {
                    mma16816(c[i][j], ah, bh[j]);
                    mma16816(c[i][j], ah, bl[j]);
                    mma16816(c[i][j], al, bh[j]);
                }
            }
        }
        __syncthreads();
        if (cch + 2 < 32) { hmma_issue(sb, cch & 1, Ah, Al, Bh, Bl, row0, col0, (cch + 2) * 32); cp_commit(); }
    }
}

// ---------------- projection GEMM: epilogue emits split-bf16 Q/K (+V transposed)
__global__ __launch_bounds__(GTHREADS, 1)
void proj_hmma() {
    extern __shared__ char sm[];
    uint32_t sb = smem_u32(sm);
    const __nv_bfloat16 *Ah, *Al, *Bh, *Bl;
    int z = blockIdx.z;
    if (z == 0)      { Ah = g_qh; Al = g_ql; Bh = g_Wqh; Bl = g_Wql; }
    else if (z == 1) { Ah = g_kh; Al = g_kl; Bh = g_Wkh; Bl = g_Wkl; }
    else             { Ah = g_vh; Al = g_vl; Bh = g_Wvh; Bl = g_Wvl; }
    int row0 = blockIdx.y * BM, col0 = blockIdx.x * BN;

    float c[2][4][4];
    hmma_gemm(sb, Ah, Al, Bh, Bl, row0, col0, c);

    int lane = threadIdx.x & 31, wid = threadIdx.x >> 5;
    int m0 = (wid >> 2) * 32, n0 = (wid & 3) * 32;
    int trow = lane >> 2, tcol = (lane & 3) * 2;
    #pragma unroll
    for (int i = 0; i < 2; i++) {
        #pragma unroll
        for (int half = 0; half < 2; half++) {
            int row = row0 + m0 + 16 * i + trow + half * 8;
            int bb = row >> 11, tt = row & 2047;
            #pragma unroll
            for (int j = 0; j < 4; j++) {
                int col = col0 + n0 + 8 * j + tcol;
                int h = col >> 6, d = col & 63;
                size_t bh_ = (size_t)bb * H + h;
                float v0 = c[i][j][half * 2 + 0];
                float v1 = c[i][j][half * 2 + 1];
                __nv_bfloat16 h0 = __float2bfloat16(v0);
                __nv_bfloat16 h1 = __float2bfloat16(v1);
                __nv_bfloat16 l0 = __float2bfloat16(v0 - __bfloat162float(h0));
                __nv_bfloat16 l1 = __float2bfloat16(v1 - __bfloat162float(h1));
                if (z == 0) {
                    size_t o = (bh_ * T + tt) * HD + d;
                    *(uint32_t*)(g_aQh + o) = pack_hilo(h0, h1);
                    *(uint32_t*)(g_aQl + o) = pack_hilo(l0, l1);
                } else if (z == 1) {
                    size_t o = (bh_ * T + tt) * HD + d;
                    *(uint32_t*)(g_aKh + o) = pack_hilo(h0, h1);
                    *(uint32_t*)(g_aKl + o) = pack_hilo(l0, l1);
                } else {
                    // V transposed: [bh][n][t]
                    size_t o0 = (bh_ * HD + d) * T + tt;
                    size_t o1 = (bh_ * HD + d + 1) * T + tt;
                    g_aVh[o0] = h0; g_aVh[o1] = h1;
                    g_aVl[o0] = l0; g_aVl[o1] = l1;
                }
            }
        }
    }
}

// ---------------- output projection GEMM + bias ----------------
__global__ __launch_bounds__(GTHREADS, 1)
void out_hmma(const float* __restrict__ bo, float* __restrict__ dout) {
    extern __shared__ char sm[];
    uint32_t sb = smem_u32(sm);
    int row0 = blockIdx.y * BM, col0 = blockIdx.x * BN;

    float c[2][4][4];
    hmma_gemm(sb, g_Oh, g_Ol, g_Woh, g_Wol, row0, col0, c);

    int lane = threadIdx.x & 31, wid = threadIdx.x >> 5;
    int m0 = (wid >> 2) * 32, n0 = (wid & 3) * 32;
    int trow = lane >> 2, tcol = (lane & 3) * 2;
    #pragma unroll
    for (int i = 0; i < 2; i++) {
        #pragma unroll
        for (int half = 0; half < 2; half++) {
            int row = row0 + m0 + 16 * i + trow + half * 8;
            #pragma unroll
            for (int j = 0; j < 4; j++) {
                int col = col0 + n0 + 8 * j + tcol;
                float2 b2 = *(const float2*)(bo + col);
                float2 v2 = make_float2(c[i][j][half * 2 + 0] + b2.x,
                                        c[i][j][half * 2 + 1] + b2.y);
                *(float2*)(dout + (size_t)row * D + col) = v2;
            }
        }
    }
}

// ---------------------------------------------------------------------------
// HMMA flash attention: CTA = 128 q-rows, 8 warps x 16 rows, BC=64 keys/chunk
// ---------------------------------------------------------------------------
#define ROWK 144                       // 64 bf16 (128B) + 16B pad
#define AQ_H 0
#define AQ_L 18432
#define KV0  36864
#define KVSTAGE 36864                  // per stage: Kh,Kl,Vh,Vl @ 9216 each
#define AK_H 0
#define AK_L 9216
#define AV_H 18432
#define AV_L 27648
#define ATT_SMEM 110592

__device__ __forceinline__ void attn_fill_kv(uint32_t st, int bh, int kc) {
    int tid = threadIdx.x;
    #pragma unroll
    for (int r = 0; r < 2; r++) {
        int idx = tid + r * 256;
        int row = idx >> 3, seg = idx & 7;
        size_t kb = ((size_t)bh * T + kc + row) * HD + seg * 8;
        size_t vb = ((size_t)bh * HD + row) * T + kc + seg * 8;
        uint32_t so = row * ROWK + seg * 16;
        cp16(st + AK_H + so, g_aKh + kb);
        cp16(st + AK_L + so, g_aKl + kb);
        cp16(st + AV_H + so, g_aVh + vb);
        cp16(st + AV_L + so, g_aVl + vb);
    }
}

__global__ __launch_bounds__(256, 1) void attn_hmma()
{
    extern __shared__ char sm[];
    uint32_t sb = smem_u32(sm);
    int bh = blockIdx.y;
    int qt0 = blockIdx.x * 128;
    int tid = threadIdx.x, lane = tid & 31, warp = tid >> 5;
    int mt = lane >> 3, lr = lane & 7, g = lane >> 2, tig = lane & 3;

    // Q tile fill (128 rows x 8 segs, hi+lo)
    {
        const __nv_bfloat16* qh = g_aQh + ((size_t)bh * T + qt0) * HD;
        const __nv_bfloat16* ql = g_aQl + ((size_t)bh * T + qt0) * HD;
        #pragma unroll
        for (int r = 0; r < 4; r++) {
            int idx = tid + r * 256;
            int row = idx >> 3, seg = idx & 7;
            cp16(sb + AQ_H + row * ROWK + seg * 16, qh + (size_t)row * HD + seg * 8);
            cp16(sb + AQ_L + row * ROWK + seg * 16, ql + (size_t)row * HD + seg * 8);
        }
    }
    attn_fill_kv(sb + KV0, bh, 0);
    cp_commit();

    float o[8][4];
    #pragma unroll
    for (int j = 0; j < 8; j++)
        #pragma unroll
        for (int f = 0; f < 4; f++) o[j][f] = 0.f;
    float m0 = -1e30f, m1 = -1e30f, l0 = 0.f, l1 = 0.f;

    uint32_t aoffQ = (uint32_t)((warp * 16 + (mt & 1) * 8 + lr) * ROWK + ((mt >> 1) * 8) * 2);
    uint32_t boff  = (uint32_t)(((mt >> 1) * 8 + lr) * ROWK + ((mt & 1) * 8) * 2);

    #pragma unroll 1
    for (int ci = 0; ci < 32; ci++) {
        if (ci + 1 < 32) {
            attn_fill_kv(sb + KV0 + ((ci + 1) & 1) * KVSTAGE, bh, (ci + 1) * 64);
            cp_commit();
            cp_wait<1>();
        } else {
            cp_wait<0>();
        }
        __syncthreads();
        uint32_t st = sb + KV0 + (ci & 1) * KVSTAGE;

        // ---- S = Q K^T (split-bf16, fp32 accum): warp computes 16x64 ----
        float s[8][4];
        #pragma unroll
        for (int j = 0; j < 8; j++)
            #pragma unroll
            for (int f = 0; f < 4; f++) s[j][f] = 0.f;

        #pragma unroll
        for (int kk = 0; kk < 64; kk += 16) {
            uint32_t ah[4], al[4];
            ldsm4(ah, sb + AQ_H + aoffQ + kk * 2);
            ldsm4(al, sb + AQ_L + aoffQ + kk * 2);
            #pragma unroll
            for (int jp = 0; jp < 4; jp++) {
                uint32_t kh[4], kl[4];
                ldsm4(kh, st + AK_H + boff + jp * 16 * ROWK + kk * 2);
                ldsm4(kl, st + AK_L + boff + jp * 16 * ROWK + kk * 2);
                mma16816(s[2*jp],   ah, kh);     mma16816(s[2*jp],   ah, kl);     mma16816(s[2*jp],   al, kh);
                mma16816(s[2*jp+1], ah, kh + 2); mma16816(s[2*jp+1], ah, kl + 2); mma16816(s[2*jp+1], al, kh + 2);
            }
        }

        // ---- online softmax (rows g, g+8 per lane; reduce over 4 lanes/row)
        float mx0 = -1e30f, mx1 = -1e30f;
        #pragma unroll
        for (int j = 0; j < 8; j++) {
            s[j][0] *= 0.125f; s[j][1] *= 0.125f; s[j][2] *= 0.125f; s[j][3] *= 0.125f;
            mx0 = fmaxf(mx0, fmaxf(s[j][0], s[j][1]));
            mx1 = fmaxf(mx1, fmaxf(s[j][2], s[j][3]));
        }
        mx0 = fmaxf(mx0, __shfl_xor_sync(0xffffffffu, mx0, 1));
        mx0 = fmaxf(mx0, __shfl_xor_sync(0xffffffffu, mx0, 2));
        mx1 = fmaxf(mx1, __shfl_xor_sync(0xffffffffu, mx1, 1));
        mx1 = fmaxf(mx1, __shfl_xor_sync(0xffffffffu, mx1, 2));
        float nm0 = fmaxf(m0, mx0), nm1 = fmaxf(m1, mx1);
        float al0 = __expf(m0 - nm0), al1 = __expf(m1 - nm1);
        m0 = nm0; m1 = nm1;
        float rs0 = 0.f, rs1 = 0.f;
        #pragma unroll
        for (int j = 0; j < 8; j++) {
            s[j][0] = __expf(s[j][0] - m0); rs0 += s[j][0];
            s[j][1] = __expf(s[j][1] - m0); rs0 += s[j][1];
            s[j][2] = __expf(s[j][2] - m1); rs1 += s[j][2];
            s[j][3] = __expf(s[j][3] - m1); rs1 += s[j][3];
        }
        rs0 += __shfl_xor_sync(0xffffffffu, rs0, 1);
        rs0 += __shfl_xor_sync(0xffffffffu, rs0, 2);
        rs1 += __shfl_xor_sync(0xffffffffu, rs1, 1);
        rs1 += __shfl_xor_sync(0xffffffffu, rs1, 2);
        l0 = l0 * al0 + rs0;
        l1 = l1 * al1 + rs1;
        #pragma unroll
        for (int j = 0; j < 8; j++) {
            o[j][0] *= al0; o[j][1] *= al0; o[j][2] *= al1; o[j][3] *= al1;
        }

        // ---- O += P V (split P, split V; C-layout == A-layout trick) ----
        #pragma unroll
        for (int j2 = 0; j2 < 4; j2++) {
            uint32_t aPh[4], aPl[4];
            #pragma unroll
            for (int q2 = 0; q2 < 2; q2++) {
                float p0 = s[2*j2+q2][0], p1 = s[2*j2+q2][1];
                float p2 = s[2*j2+q2][2], p3 = s[2*j2+q2][3];
                __nv_bfloat16 h0 = __float2bfloat16(p0), h1 = __float2bfloat16(p1);
                __nv_bfloat16 h2 = __float2bfloat16(p2), h3 = __float2bfloat16(p3);
                aPh[q2*2+0] = pack_hilo(h0, h1);
                aPh[q2*2+1] = pack_hilo(h2, h3);
                aPl[q2*2+0] = pack_hilo(__float2bfloat16(p0 - __bfloat162float(h0)),
                                        __float2bfloat16(p1 - __bfloat162float(h1)));
                aPl[q2*2+1] = pack_hilo(__float2bfloat16(p2 - __bfloat162float(h2)),
                                        __float2bfloat16(p3 - __bfloat162float(h3)));
            }
            #pragma unroll
            for (int dp = 0; dp < 4; dp++) {
                uint32_t vh[4], vl[4];
                ldsm4(vh, st + AV_H + boff + dp * 16 * ROWK + j2 * 32);
                ldsm4(vl, st + AV_L + boff + dp * 16 * ROWK + j2 * 32);
                mma16816(o[2*dp],   aPh, vh);     mma16816(o[2*dp],   aPh, vl);     mma16816(o[2*dp],   aPl, vh);
                mma16816(o[2*dp+1], aPh, vh + 2); mma16816(o[2*dp+1], aPh, vl + 2); mma16816(o[2*dp+1], aPl, vh + 2);
            }
        }
        __syncthreads();
    }

    // ---- epilogue: O/l -> bf16 hi/lo at [b][t][h*64+d] ----
    float inv0 = 1.f / l0, inv1 = 1.f / l1;
    int b = bh >> 4, h = bh & 15;
    int tA = qt0 + warp * 16 + g;
    int tB = tA + 8;
    #pragma unroll
    for (int j = 0; j < 8; j++) {
        int d = h * 64 + 8 * j + 2 * tig;
        {
            float x0 = o[j][0] * inv0, x1 = o[j][1] * inv0;
            __nv_bfloat16 h0 = __float2bfloat16(x0), h1 = __float2bfloat16(x1);
            size_t off = ((size_t)b * T + tA) * D + d;
            *(uint32_t*)(g_Oh + off) = pack_hilo(h0, h1);
            *(uint32_t*)(g_Ol + off) = pack_hilo(__float2bfloat16(x0 - __bfloat162float(h0)),
                                                 __float2bfloat16(x1 - __bfloat162float(h1)));
        }
        {
            float y0 = o[j][2] * inv1, y1 = o[j][3] * inv1;
            __nv_bfloat16 h0 = __float2bfloat16(y0), h1 = __float2bfloat16(y1);
            size_t off = ((size_t)b * T + tB) * D + d;
            *(uint32_t*)(g_Oh + off) = pack_hilo(h0, h1);
            *(uint32_t*)(g_Ol + off) = pack_hilo(__float2bfloat16(y0 - __bfloat162float(h0)),
                                                 __float2bfloat16(y1 - __bfloat162float(h1)));
        }
    }
}

// ---------------------------------------------------------------------------
extern "C" void kernel_launch(void* const* d_in, const int* in_sizes, int n_in,
                              void* d_out, int out_size)
{
    const float* k  = (const float*)d_in[0];
    const float* q  = (const float*)d_in[1];
    const float* v  = (const float*)d_in[2];
    const float* Wk = (const float*)d_in[3];
    const float* Wq = (const float*)d_in[4];
    const float* Wv = (const float*)d_in[5];
    const float* Wo = (const float*)d_in[6];
    const float* bo = (const float*)d_in[7];
    float* out = (float*)d_out;

    cudaFuncSetAttribute(proj_hmma, cudaFuncAttributeMaxDynamicSharedMemorySize, GEMM_SMEM);
    cudaFuncSetAttribute(out_hmma,  cudaFuncAttributeMaxDynamicSharedMemorySize, GEMM_SMEM);
    cudaFuncSetAttribute(attn_hmma, cudaFuncAttributeMaxDynamicSharedMemorySize, ATT_SMEM);

    // 1) split inputs/weights into bf16 hi/lo
    cvt_all<<<16384, 256>>>(q, k, v, Wq, Wk, Wv, Wo);

    // 2) Q/K/V projections (tensor cores); epilogue emits split-bf16 Q/K + V^T
    proj_hmma<<<dim3(D/BN, (BATCH*T)/BM, 3), GTHREADS, GEMM_SMEM>>>();

    // 3) flash attention on tensor cores (split-bf16 S and PV)
    attn_hmma<<<dim3(T/128, BATCH*H), 256, ATT_SMEM>>>();

    // 4) output projection + bias (tensor cores)
    out_hmma<<<dim3(D/BN, (BATCH*T)/BM), GTHREADS, GEMM_SMEM>>>(bo, out);
}

// round 13
// speedup vs baseline: 3.5863x; 1.0520x over previous
#include <cuda_runtime.h>
#include <cuda_bf16.h>
#include <cstdint>

#define BATCH 2
#define T 2048
#define D 1024
#define H 16
#define HD 64

// ---------------- scratch (allocation-free) ----------------
__device__ __nv_bfloat16 g_qh[BATCH*T*D], g_ql[BATCH*T*D];
__device__ __nv_bfloat16 g_kh[BATCH*T*D], g_kl[BATCH*T*D];
__device__ __nv_bfloat16 g_vh[BATCH*T*D], g_vl[BATCH*T*D];
__device__ __nv_bfloat16 g_Wqh[D*D], g_Wql[D*D];
__device__ __nv_bfloat16 g_Wkh[D*D], g_Wkl[D*D];
__device__ __nv_bfloat16 g_Wvh[D*D], g_Wvl[D*D];
__device__ __nv_bfloat16 g_Woh[D*D], g_Wol[D*D];
// projected Q/K (split, [bh][t][n]) and V (split, TRANSPOSED [bh][n][t])
__device__ __nv_bfloat16 g_aQh[BATCH*H*T*HD], g_aQl[BATCH*H*T*HD];
__device__ __nv_bfloat16 g_aKh[BATCH*H*T*HD], g_aKl[BATCH*H*T*HD];
__device__ __nv_bfloat16 g_aVh[BATCH*H*T*HD], g_aVl[BATCH*H*T*HD];
// attention output (split, [b][t][h*64+d])
__device__ __nv_bfloat16 g_Oh[BATCH*T*D], g_Ol[BATCH*T*D];

// ---------------- PTX helpers (family-portable: sm_80+ only) ----------------
__device__ __forceinline__ uint32_t smem_u32(const void* p) {
    uint32_t a;
    asm("{ .reg .u64 t; cvta.to.shared.u64 t, %1; cvt.u32.u64 %0, t; }" : "=r"(a) : "l"(p));
    return a;
}
__device__ __forceinline__ void cp16(uint32_t s, const void* g) {
    asm volatile("cp.async.cg.shared.global [%0], [%1], 16;" :: "r"(s), "l"(g));
}
__device__ __forceinline__ void cp_commit() {
    asm volatile("cp.async.commit_group;" ::: "memory");
}
template<int N> __device__ __forceinline__ void cp_wait() {
    asm volatile("cp.async.wait_group %0;" :: "n"(N) : "memory");
}
__device__ __forceinline__ void ldsm4(uint32_t* r, uint32_t addr) {
    asm volatile("ldmatrix.sync.aligned.m8n8.x4.shared.b16 {%0,%1,%2,%3}, [%4];"
                 : "=r"(r[0]), "=r"(r[1]), "=r"(r[2]), "=r"(r[3]) : "r"(addr));
}
__device__ __forceinline__ void mma16816(float* c, const uint32_t* a, const uint32_t* b) {
    asm volatile(
        "mma.sync.aligned.m16n8k16.row.col.f32.bf16.bf16.f32 "
        "{%0,%1,%2,%3}, {%4,%5,%6,%7}, {%8,%9}, {%0,%1,%2,%3};"
        : "+f"(c[0]), "+f"(c[1]), "+f"(c[2]), "+f"(c[3])
        : "r"(a[0]), "r"(a[1]), "r"(a[2]), "r"(a[3]), "r"(b[0]), "r"(b[1]));
}
__device__ __forceinline__ uint32_t pack_hilo(__nv_bfloat16 lo, __nv_bfloat16 hi) {
    __nv_bfloat162 t(lo, hi);
    return *(uint32_t*)&t;
}

// ---------------- GEMM geometry (BK=64, 2-stage) ----------------
#define BM 128
#define BN 128
#define BK 64
#define ROWB 144                   // 64 bf16 (128B) + 16B pad; 9*16B coprime 8 -> conflict-free
#define TILE_SMEM (128 * ROWB)     // 18432 B per operand tile
#define BUF_BYTES (4 * TILE_SMEM)  // Ah, Al, Bh, Bl = 73728 B
#define GEMM_SMEM (2 * BUF_BYTES)  // 147456 B
#define GTHREADS 512
#define NCHUNK (D / BK)            // 16

// ---------------- fused split convert: fp32 -> (hi, lo) bf16 ----------------
__global__ __launch_bounds__(256) void cvt_all(
    const float* __restrict__ q, const float* __restrict__ k, const float* __restrict__ v,
    const float* __restrict__ Wq, const float* __restrict__ Wk,
    const float* __restrict__ Wv, const float* __restrict__ Wo)
{
    int b = blockIdx.x;
    const float* src; __nv_bfloat16 *hi, *lo; int lb;
    if (b < 4096)       { src = q;  hi = g_qh;  lo = g_ql;  lb = b; }
    else if (b < 8192)  { src = k;  hi = g_kh;  lo = g_kl;  lb = b - 4096; }
    else if (b < 12288) { src = v;  hi = g_vh;  lo = g_vl;  lb = b - 8192; }
    else if (b < 13312) { src = Wq; hi = g_Wqh; lo = g_Wql; lb = b - 12288; }
    else if (b < 14336) { src = Wk; hi = g_Wkh; lo = g_Wkl; lb = b - 13312; }
    else if (b < 15360) { src = Wv; hi = g_Wvh; lo = g_Wvl; lb = b - 14336; }
    else                { src = Wo; hi = g_Woh; lo = g_Wol; lb = b - 15360; }
    int i = lb * 1024 + threadIdx.x * 4;
    float4 vv4 = *(const float4*)(src + i);
    float vv[4] = {vv4.x, vv4.y, vv4.z, vv4.w};
    __nv_bfloat16 h[4], l[4];
    #pragma unroll
    for (int j = 0; j < 4; j++) {
        h[j] = __float2bfloat16(vv[j]);
        l[j] = __float2bfloat16(vv[j] - __bfloat162float(h[j]));
    }
    *(__nv_bfloat162*)(hi + i)     = __nv_bfloat162(h[0], h[1]);
    *(__nv_bfloat162*)(hi + i + 2) = __nv_bfloat162(h[2], h[3]);
    *(__nv_bfloat162*)(lo + i)     = __nv_bfloat162(l[0], l[1]);
    *(__nv_bfloat162*)(lo + i + 2) = __nv_bfloat162(l[2], l[3]);
}

// ---------------- shared HMMA mainloop (128x128, BK=64, split-bf16) --------
__device__ __forceinline__ void hmma_issue(
    uint32_t sb, int buf,
    const __nv_bfloat16* __restrict__ Ah, const __nv_bfloat16* __restrict__ Al,
    const __nv_bfloat16* __restrict__ Bh, const __nv_bfloat16* __restrict__ Bl,
    int row0, int col0, int kc)
{
    int tid = threadIdx.x;
    const __nv_bfloat16* srcs[4] = {Ah, Al, Bh, Bl};
    int bases[4] = {row0, row0, col0, col0};
    #pragma unroll
    for (int t = 0; t < 4; t++) {
        #pragma unroll
        for (int j = 0; j < 2; j++) {
            int idx = tid + j * 512;          // 0..1023 : 128 rows x 8 segs
            int row = idx >> 3, seg = idx & 7;
            cp16(sb + buf * BUF_BYTES + t * TILE_SMEM + row * ROWB + seg * 16,
                 srcs[t] + (size_t)(bases[t] + row) * D + kc + seg * 8);
        }
    }
}

__device__ __forceinline__ void hmma_gemm(
    uint32_t sb,
    const __nv_bfloat16* __restrict__ Ah, const __nv_bfloat16* __restrict__ Al,
    const __nv_bfloat16* __restrict__ Bh, const __nv_bfloat16* __restrict__ Bl,
    int row0, int col0, float c[2][4][4])
{
    int tid = threadIdx.x;
    int lane = tid & 31, wid = tid >> 5;
    int m0 = (wid >> 2) * 32, n0 = (wid & 3) * 32;
    int mt = lane >> 3, lr = lane & 7;
    uint32_t aoff = (uint32_t)((m0 + (mt & 1) * 8 + lr) * ROWB + ((mt >> 1) * 8) * 2);
    uint32_t boff = (uint32_t)((n0 + (mt >> 1) * 8 + lr) * ROWB + ((mt & 1) * 8) * 2);

    #pragma unroll
    for (int i = 0; i < 2; i++)
        #pragma unroll
        for (int j = 0; j < 4; j++)
            #pragma unroll
            for (int f = 0; f < 4; f++) c[i][j][f] = 0.f;

    hmma_issue(sb, 0, Ah, Al, Bh, Bl, row0, col0, 0);  cp_commit();
    hmma_issue(sb, 1, Ah, Al, Bh, Bl, row0, col0, BK); cp_commit();

    #pragma unroll 1
    for (int cch = 0; cch < NCHUNK; cch++) {
        if (cch < NCHUNK - 1) cp_wait<1>(); else cp_wait<0>();
        __syncthreads();
        uint32_t bufb = sb + (cch & 1) * BUF_BYTES;

        #pragma unroll
        for (int kk = 0; kk < BK; kk += 16) {
            uint32_t bh[4][2], bl[4][2];
            #pragma unroll
            for (int jp = 0; jp < 2; jp++) {
                uint32_t r[4];
                ldsm4(r, bufb + 2 * TILE_SMEM + boff + jp * 16 * ROWB + kk * 2);
                bh[2*jp][0] = r[0]; bh[2*jp][1] = r[1];
                bh[2*jp+1][0] = r[2]; bh[2*jp+1][1] = r[3];
                ldsm4(r, bufb + 3 * TILE_SMEM + boff + jp * 16 * ROWB + kk * 2);
                bl[2*jp][0] = r[0]; bl[2*jp][1] = r[1];
                bl[2*jp+1][0] = r[2]; bl[2*jp+1][1] = r[3];
            }
            #pragma unroll
            for (int i = 0; i < 2; i++) {
                uint32_t ah[4], al[4];
                ldsm4(ah, bufb + 0 * TILE_SMEM + aoff + i * 16 * ROWB + kk * 2);
                ldsm4(al, bufb + 1 * TILE_SMEM + aoff + i * 16 * ROWB + kk * 2);
                #pragma unroll
                for (int j = 0; j < 4; j++) {
                    mma16816(c[i][j], ah, bh[j]);
                    mma16816(c[i][j], ah, bl[j]);
                    mma16816(c[i][j], al, bh[j]);
                }
            }
        }
        __syncthreads();
        if (cch + 2 < NCHUNK) { hmma_issue(sb, cch & 1, Ah, Al, Bh, Bl, row0, col0, (cch + 2) * BK); cp_commit(); }
    }
}

// ---------------- projection GEMM: epilogue emits split-bf16 Q/K (+V transposed)
__global__ __launch_bounds__(GTHREADS, 1)
void proj_hmma() {
    extern __shared__ char sm[];
    uint32_t sb = smem_u32(sm);
    const __nv_bfloat16 *Ah, *Al, *Bh, *Bl;
    int z = blockIdx.z;
    if (z == 0)      { Ah = g_qh; Al = g_ql; Bh = g_Wqh; Bl = g_Wql; }
    else if (z == 1) { Ah = g_kh; Al = g_kl; Bh = g_Wkh; Bl = g_Wkl; }
    else             { Ah = g_vh; Al = g_vl; Bh = g_Wvh; Bl = g_Wvl; }
    int row0 = blockIdx.y * BM, col0 = blockIdx.x * BN;

    float c[2][4][4];
    hmma_gemm(sb, Ah, Al, Bh, Bl, row0, col0, c);

    int lane = threadIdx.x & 31, wid = threadIdx.x >> 5;
    int m0 = (wid >> 2) * 32, n0 = (wid & 3) * 32;
    int trow = lane >> 2, tcol = (lane & 3) * 2;
    #pragma unroll
    for (int i = 0; i < 2; i++) {
        #pragma unroll
        for (int half = 0; half < 2; half++) {
            int row = row0 + m0 + 16 * i + trow + half * 8;
            int bb = row >> 11, tt = row & 2047;
            #pragma unroll
            for (int j = 0; j < 4; j++) {
                int col = col0 + n0 + 8 * j + tcol;
                int h = col >> 6, d = col & 63;
                size_t bh_ = (size_t)bb * H + h;
                float v0 = c[i][j][half * 2 + 0];
                float v1 = c[i][j][half * 2 + 1];
                __nv_bfloat16 h0 = __float2bfloat16(v0);
                __nv_bfloat16 h1 = __float2bfloat16(v1);
                __nv_bfloat16 l0 = __float2bfloat16(v0 - __bfloat162float(h0));
                __nv_bfloat16 l1 = __float2bfloat16(v1 - __bfloat162float(h1));
                if (z == 0) {
                    size_t o = (bh_ * T + tt) * HD + d;
                    *(uint32_t*)(g_aQh + o) = pack_hilo(h0, h1);
                    *(uint32_t*)(g_aQl + o) = pack_hilo(l0, l1);
                } else if (z == 1) {
                    size_t o = (bh_ * T + tt) * HD + d;
                    *(uint32_t*)(g_aKh + o) = pack_hilo(h0, h1);
                    *(uint32_t*)(g_aKl + o) = pack_hilo(l0, l1);
                } else {
                    // V transposed: [bh][n][t]
                    size_t o0 = (bh_ * HD + d) * T + tt;
                    size_t o1 = (bh_ * HD + d + 1) * T + tt;
                    g_aVh[o0] = h0; g_aVh[o1] = h1;
                    g_aVl[o0] = l0; g_aVl[o1] = l1;
                }
            }
        }
    }
}

// ---------------- output projection GEMM + bias ----------------
__global__ __launch_bounds__(GTHREADS, 1)
void out_hmma(const float* __restrict__ bo, float* __restrict__ dout) {
    extern __shared__ char sm[];
    uint32_t sb = smem_u32(sm);
    int row0 = blockIdx.y * BM, col0 = blockIdx.x * BN;

    float c[2][4][4];
    hmma_gemm(sb, g_Oh, g_Ol, g_Woh, g_Wol, row0, col0, c);

    int lane = threadIdx.x & 31, wid = threadIdx.x >> 5;
    int m0 = (wid >> 2) * 32, n0 = (wid & 3) * 32;
    int trow = lane >> 2, tcol = (lane & 3) * 2;
    #pragma unroll
    for (int i = 0; i < 2; i++) {
        #pragma unroll
        for (int half = 0; half < 2; half++) {
            int row = row0 + m0 + 16 * i + trow + half * 8;
            #pragma unroll
            for (int j = 0; j < 4; j++) {
                int col = col0 + n0 + 8 * j + tcol;
                float2 b2 = *(const float2*)(bo + col);
                float2 v2 = make_float2(c[i][j][half * 2 + 0] + b2.x,
                                        c[i][j][half * 2 + 1] + b2.y);
                *(float2*)(dout + (size_t)row * D + col) = v2;
            }
        }
    }
}

// ---------------------------------------------------------------------------
// HMMA flash attention: CTA = 128 q-rows, 8 warps x 16 rows, BC=64 keys/chunk
// 3-stage KV pipeline (prefetch distance 2)
// ---------------------------------------------------------------------------
#define ROWK 144                       // 64 bf16 (128B) + 16B pad
#define AQ_H 0
#define AQ_L 18432
#define KV0  36864
#define KVSTAGE 36864                  // per stage: Kh,Kl,Vh,Vl @ 9216 each
#define AK_H 0
#define AK_L 9216
#define AV_H 18432
#define AV_L 27648
#define ATT_SMEM (KV0 + 3 * KVSTAGE)   // 147456

__device__ __forceinline__ void attn_fill_kv(uint32_t st, int bh, int kc) {
    int tid = threadIdx.x;
    #pragma unroll
    for (int r = 0; r < 2; r++) {
        int idx = tid + r * 256;
        int row = idx >> 3, seg = idx & 7;
        size_t kb = ((size_t)bh * T + kc + row) * HD + seg * 8;
        size_t vb = ((size_t)bh * HD + row) * T + kc + seg * 8;
        uint32_t so = row * ROWK + seg * 16;
        cp16(st + AK_H + so, g_aKh + kb);
        cp16(st + AK_L + so, g_aKl + kb);
        cp16(st + AV_H + so, g_aVh + vb);
        cp16(st + AV_L + so, g_aVl + vb);
    }
}

__global__ __launch_bounds__(256, 1) void attn_hmma()
{
    extern __shared__ char sm[];
    uint32_t sb = smem_u32(sm);
    int bh = blockIdx.y;
    int qt0 = blockIdx.x * 128;
    int tid = threadIdx.x, lane = tid & 31, warp = tid >> 5;
    int mt = lane >> 3, lr = lane & 7, g = lane >> 2, tig = lane & 3;

    // Q tile fill (128 rows x 8 segs, hi+lo) — grouped with KV stage 0
    {
        const __nv_bfloat16* qh = g_aQh + ((size_t)bh * T + qt0) * HD;
        const __nv_bfloat16* ql = g_aQl + ((size_t)bh * T + qt0) * HD;
        #pragma unroll
        for (int r = 0; r < 4; r++) {
            int idx = tid + r * 256;
            int row = idx >> 3, seg = idx & 7;
            cp16(sb + AQ_H + row * ROWK + seg * 16, qh + (size_t)row * HD + seg * 8);
            cp16(sb + AQ_L + row * ROWK + seg * 16, ql + (size_t)row * HD + seg * 8);
        }
    }
    attn_fill_kv(sb + KV0, bh, 0);
    cp_commit();                                   // G0 = {Q, KV0}
    attn_fill_kv(sb + KV0 + KVSTAGE, bh, 64);
    cp_commit();                                   // G1 = {KV1}

    float o[8][4];
    #pragma unroll
    for (int j = 0; j < 8; j++)
        #pragma unroll
        for (int f = 0; f < 4; f++) o[j][f] = 0.f;
    float m0 = -1e30f, m1 = -1e30f, l0 = 0.f, l1 = 0.f;

    uint32_t aoffQ = (uint32_t)((warp * 16 + (mt & 1) * 8 + lr) * ROWK + ((mt >> 1) * 8) * 2);
    uint32_t boff  = (uint32_t)(((mt >> 1) * 8 + lr) * ROWK + ((mt & 1) * 8) * 2);

    #pragma unroll 1
    for (int ci = 0; ci < 32; ci++) {
        if (ci + 2 < 32) {
            // buffer (ci+2)%3 was last read in chunk ci-1; trailing sync protects it
            attn_fill_kv(sb + KV0 + ((ci + 2) % 3) * KVSTAGE, bh, (ci + 2) * 64);
            cp_commit();
            cp_wait<2>();                          // fill(ci) complete
        } else {
            cp_wait<0>();
        }
        __syncthreads();
        uint32_t st = sb + KV0 + (ci % 3) * KVSTAGE;

        // ---- S = Q K^T (split-bf16, fp32 accum): warp computes 16x64 ----
        float s[8][4];
        #pragma unroll
        for (int j = 0; j < 8; j++)
            #pragma unroll
            for (int f = 0; f < 4; f++) s[j][f] = 0.f;

        #pragma unroll
        for (int kk = 0; kk < 64; kk += 16) {
            uint32_t ah[4], al[4];
            ldsm4(ah, sb + AQ_H + aoffQ + kk * 2);
            ldsm4(al, sb + AQ_L + aoffQ + kk * 2);
            #pragma unroll
            for (int jp = 0; jp < 4; jp++) {
                uint32_t kh[4], kl[4];
                ldsm4(kh, st + AK_H + boff + jp * 16 * ROWK + kk * 2);
                ldsm4(kl, st + AK_L + boff + jp * 16 * ROWK + kk * 2);
                mma16816(s[2*jp],   ah, kh);     mma16816(s[2*jp],   ah, kl);     mma16816(s[2*jp],   al, kh);
                mma16816(s[2*jp+1], ah, kh + 2); mma16816(s[2*jp+1], ah, kl + 2); mma16816(s[2*jp+1], al, kh + 2);
            }
        }

        // ---- online softmax (rows g, g+8 per lane; reduce over 4 lanes/row)
        float mx0 = -1e30f, mx1 = -1e30f;
        #pragma unroll
        for (int j = 0; j < 8; j++) {
            s[j][0] *= 0.125f; s[j][1] *= 0.125f; s[j][2] *= 0.125f; s[j][3] *= 0.125f;
            mx0 = fmaxf(mx0, fmaxf(s[j][0], s[j][1]));
            mx1 = fmaxf(mx1, fmaxf(s[j][2], s[j][3]));
        }
        mx0 = fmaxf(mx0, __shfl_xor_sync(0xffffffffu, mx0, 1));
        mx0 = fmaxf(mx0, __shfl_xor_sync(0xffffffffu, mx0, 2));
        mx1 = fmaxf(mx1, __shfl_xor_sync(0xffffffffu, mx1, 1));
        mx1 = fmaxf(mx1, __shfl_xor_sync(0xffffffffu, mx1, 2));
        float nm0 = fmaxf(m0, mx0), nm1 = fmaxf(m1, mx1);
        float al0 = __expf(m0 - nm0), al1 = __expf(m1 - nm1);
        m0 = nm0; m1 = nm1;
        float rs0 = 0.f, rs1 = 0.f;
        #pragma unroll
        for (int j = 0; j < 8; j++) {
            s[j][0] = __expf(s[j][0] - m0); rs0 += s[j][0];
            s[j][1] = __expf(s[j][1] - m0); rs0 += s[j][1];
            s[j][2] = __expf(s[j][2] - m1); rs1 += s[j][2];
            s[j][3] = __expf(s[j][3] - m1); rs1 += s[j][3];
        }
        rs0 += __shfl_xor_sync(0xffffffffu, rs0, 1);
        rs0 += __shfl_xor_sync(0xffffffffu, rs0, 2);
        rs1 += __shfl_xor_sync(0xffffffffu, rs1, 1);
        rs1 += __shfl_xor_sync(0xffffffffu, rs1, 2);
        l0 = l0 * al0 + rs0;
        l1 = l1 * al1 + rs1;
        #pragma unroll
        for (int j = 0; j < 8; j++) {
            o[j][0] *= al0; o[j][1] *= al0; o[j][2] *= al1; o[j][3] *= al1;
        }

        // ---- O += P V (split P, split V; C-layout == A-layout trick) ----
        #pragma unroll
        for (int j2 = 0; j2 < 4; j2++) {
            uint32_t aPh[4], aPl[4];
            #pragma unroll
            for (int q2 = 0; q2 < 2; q2++) {
                float p0 = s[2*j2+q2][0], p1 = s[2*j2+q2][1];
                float p2 = s[2*j2+q2][2], p3 = s[2*j2+q2][3];
                __nv_bfloat16 h0 = __float2bfloat16(p0), h1 = __float2bfloat16(p1);
                __nv_bfloat16 h2 = __float2bfloat16(p2), h3 = __float2bfloat16(p3);
                aPh[q2*2+0] = pack_hilo(h0, h1);
                aPh[q2*2+1] = pack_hilo(h2, h3);
                aPl[q2*2+0] = pack_hilo(__float2bfloat16(p0 - __bfloat162float(h0)),
                                        __float2bfloat16(p1 - __bfloat162float(h1)));
                aPl[q2*2+1] = pack_hilo(__float2bfloat16(p2 - __bfloat162float(h2)),
                                        __float2bfloat16(p3 - __bfloat162float(h3)));
            }
            #pragma unroll
            for (int dp = 0; dp < 4; dp++) {
                uint32_t vh[4], vl[4];
                ldsm4(vh, st + AV_H + boff + dp * 16 * ROWK + j2 * 32);
                ldsm4(vl, st + AV_L + boff + dp * 16 * ROWK + j2 * 32);
                mma16816(o[2*dp],   aPh, vh);     mma16816(o[2*dp],   aPh, vl);     mma16816(o[2*dp],   aPl, vh);
                mma16816(o[2*dp+1], aPh, vh + 2); mma16816(o[2*dp+1], aPh, vl + 2); mma16816(o[2*dp+1], aPl, vh + 2);
            }
        }
        __syncthreads();
    }

    // ---- epilogue: O/l -> bf16 hi/lo at [b][t][h*64+d] ----
    float inv0 = 1.f / l0, inv1 = 1.f / l1;
    int b = bh >> 4, h = bh & 15;
    int tA = qt0 + warp * 16 + g;
    int tB = tA + 8;
    #pragma unroll
    for (int j = 0; j < 8; j++) {
        int d = h * 64 + 8 * j + 2 * tig;
        {
            float x0 = o[j][0] * inv0, x1 = o[j][1] * inv0;
            __nv_bfloat16 h0 = __float2bfloat16(x0), h1 = __float2bfloat16(x1);
            size_t off = ((size_t)b * T + tA) * D + d;
            *(uint32_t*)(g_Oh + off) = pack_hilo(h0, h1);
            *(uint32_t*)(g_Ol + off) = pack_hilo(__float2bfloat16(x0 - __bfloat162float(h0)),
                                                 __float2bfloat16(x1 - __bfloat162float(h1)));
        }
        {
            float y0 = o[j][2] * inv1, y1 = o[j][3] * inv1;
            __nv_bfloat16 h0 = __float2bfloat16(y0), h1 = __float2bfloat16(y1);
            size_t off = ((size_t)b * T + tB) * D + d;
            *(uint32_t*)(g_Oh + off) = pack_hilo(h0, h1);
            *(uint32_t*)(g_Ol + off) = pack_hilo(__float2bfloat16(y0 - __bfloat162float(h0)),
                                                 __float2bfloat16(y1 - __bfloat162float(h1)));
        }
    }
}

// ---------------------------------------------------------------------------
extern "C" void kernel_launch(void* const* d_in, const int* in_sizes, int n_in,
                              void* d_out, int out_size)
{
    const float* k  = (const float*)d_in[0];
    const float* q  = (const float*)d_in[1];
    const float* v  = (const float*)d_in[2];
    const float* Wk = (const float*)d_in[3];
    const float* Wq = (const float*)d_in[4];
    const float* Wv = (const float*)d_in[5];
    const float* Wo = (const float*)d_in[6];
    const float* bo = (const float*)d_in[7];
    float* out = (float*)d_out;

    cudaFuncSetAttribute(proj_hmma, cudaFuncAttributeMaxDynamicSharedMemorySize, GEMM_SMEM);
    cudaFuncSetAttribute(out_hmma,  cudaFuncAttributeMaxDynamicSharedMemorySize, GEMM_SMEM);
    cudaFuncSetAttribute(attn_hmma, cudaFuncAttributeMaxDynamicSharedMemorySize, ATT_SMEM);

    // 1) split inputs/weights into bf16 hi/lo
    cvt_all<<<16384, 256>>>(q, k, v, Wq, Wk, Wv, Wo);

    // 2) Q/K/V projections (tensor cores); epilogue emits split-bf16 Q/K + V^T
    proj_hmma<<<dim3(D/BN, (BATCH*T)/BM, 3), GTHREADS, GEMM_SMEM>>>();

    // 3) flash attention on tensor cores (split-bf16 S and PV), 3-stage pipeline
    attn_hmma<<<dim3(T/128, BATCH*H), 256, ATT_SMEM>>>();

    // 4) output projection + bias (tensor cores)
    out_hmma<<<dim3(D/BN, (BATCH*T)/BM), GTHREADS, GEMM_SMEM>>>(bo, out);
}

// round 14
// speedup vs baseline: 3.8540x; 1.0747x over previous
#include <cuda_runtime.h>
#include <cuda_bf16.h>
#include <cstdint>

#define BATCH 2
#define T 2048
#define D 1024
#define H 16
#define HD 64

// ---------------- scratch (allocation-free) ----------------
__device__ __nv_bfloat16 g_qh[BATCH*T*D], g_ql[BATCH*T*D];
__device__ __nv_bfloat16 g_kh[BATCH*T*D], g_kl[BATCH*T*D];
__device__ __nv_bfloat16 g_vh[BATCH*T*D], g_vl[BATCH*T*D];
__device__ __nv_bfloat16 g_Wqh[D*D], g_Wql[D*D];
__device__ __nv_bfloat16 g_Wkh[D*D], g_Wkl[D*D];
__device__ __nv_bfloat16 g_Wvh[D*D], g_Wvl[D*D];
__device__ __nv_bfloat16 g_Woh[D*D], g_Wol[D*D];
// projected Q/K (split, [bh][t][n]) and V (split, TRANSPOSED [bh][n][t])
__device__ __nv_bfloat16 g_aQh[BATCH*H*T*HD], g_aQl[BATCH*H*T*HD];
__device__ __nv_bfloat16 g_aKh[BATCH*H*T*HD], g_aKl[BATCH*H*T*HD];
__device__ __nv_bfloat16 g_aVh[BATCH*H*T*HD], g_aVl[BATCH*H*T*HD];
// attention output (split, [b][t][h*64+d])
__device__ __nv_bfloat16 g_Oh[BATCH*T*D], g_Ol[BATCH*T*D];

// ---------------- PTX helpers (family-portable: sm_80+ only) ----------------
__device__ __forceinline__ uint32_t smem_u32(const void* p) {
    uint32_t a;
    asm("{ .reg .u64 t; cvta.to.shared.u64 t, %1; cvt.u32.u64 %0, t; }" : "=r"(a) : "l"(p));
    return a;
}
__device__ __forceinline__ void cp16(uint32_t s, const void* g) {
    asm volatile("cp.async.cg.shared.global [%0], [%1], 16;" :: "r"(s), "l"(g));
}
__device__ __forceinline__ void cp_commit() {
    asm volatile("cp.async.commit_group;" ::: "memory");
}
template<int N> __device__ __forceinline__ void cp_wait() {
    asm volatile("cp.async.wait_group %0;" :: "n"(N) : "memory");
}
__device__ __forceinline__ void ldsm4(uint32_t* r, uint32_t addr) {
    asm volatile("ldmatrix.sync.aligned.m8n8.x4.shared.b16 {%0,%1,%2,%3}, [%4];"
                 : "=r"(r[0]), "=r"(r[1]), "=r"(r[2]), "=r"(r[3]) : "r"(addr));
}
__device__ __forceinline__ void mma16816(float* c, const uint32_t* a, const uint32_t* b) {
    asm volatile(
        "mma.sync.aligned.m16n8k16.row.col.f32.bf16.bf16.f32 "
        "{%0,%1,%2,%3}, {%4,%5,%6,%7}, {%8,%9}, {%0,%1,%2,%3};"
        : "+f"(c[0]), "+f"(c[1]), "+f"(c[2]), "+f"(c[3])
        : "r"(a[0]), "r"(a[1]), "r"(a[2]), "r"(a[3]), "r"(b[0]), "r"(b[1]));
}
__device__ __forceinline__ uint32_t pack_hilo(__nv_bfloat16 lo, __nv_bfloat16 hi) {
    __nv_bfloat162 t(lo, hi);
    return *(uint32_t*)&t;
}

// ---------------- GEMM geometry (BM=128, BN=64, BK=64, 2 CTAs/SM) ----------
#define BM 128
#define BN 64
#define BK 64
#define ROWB 144                    // 64 bf16 (128B) + 16B pad; conflict-free ldmatrix
#define A_TILE (128 * ROWB)         // 18432
#define B_TILE (64 * ROWB)          // 9216
#define GA_H 0
#define GA_L A_TILE
#define GB_H (2 * A_TILE)
#define GB_L (2 * A_TILE + B_TILE)
#define BUF_BYTES (2 * A_TILE + 2 * B_TILE)   // 55296
#define GEMM_SMEM (2 * BUF_BYTES)             // 110592
#define GTHREADS 256
#define NCHUNK (D / BK)             // 16

// ---------------- fused split convert: fp32 -> (hi, lo) bf16 ----------------
__global__ __launch_bounds__(256) void cvt_all(
    const float* __restrict__ q, const float* __restrict__ k, const float* __restrict__ v,
    const float* __restrict__ Wq, const float* __restrict__ Wk,
    const float* __restrict__ Wv, const float* __restrict__ Wo)
{
    int b = blockIdx.x;
    const float* src; __nv_bfloat16 *hi, *lo; int lb;
    if (b < 4096)       { src = q;  hi = g_qh;  lo = g_ql;  lb = b; }
    else if (b < 8192)  { src = k;  hi = g_kh;  lo = g_kl;  lb = b - 4096; }
    else if (b < 12288) { src = v;  hi = g_vh;  lo = g_vl;  lb = b - 8192; }
    else if (b < 13312) { src = Wq; hi = g_Wqh; lo = g_Wql; lb = b - 12288; }
    else if (b < 14336) { src = Wk; hi = g_Wkh; lo = g_Wkl; lb = b - 13312; }
    else if (b < 15360) { src = Wv; hi = g_Wvh; lo = g_Wvl; lb = b - 14336; }
    else                { src = Wo; hi = g_Woh; lo = g_Wol; lb = b - 15360; }
    int i = lb * 1024 + threadIdx.x * 4;
    float4 vv4 = *(const float4*)(src + i);
    float vv[4] = {vv4.x, vv4.y, vv4.z, vv4.w};
    __nv_bfloat16 h[4], l[4];
    #pragma unroll
    for (int j = 0; j < 4; j++) {
        h[j] = __float2bfloat16(vv[j]);
        l[j] = __float2bfloat16(vv[j] - __bfloat162float(h[j]));
    }
    *(__nv_bfloat162*)(hi + i)     = __nv_bfloat162(h[0], h[1]);
    *(__nv_bfloat162*)(hi + i + 2) = __nv_bfloat162(h[2], h[3]);
    *(__nv_bfloat162*)(lo + i)     = __nv_bfloat162(l[0], l[1]);
    *(__nv_bfloat162*)(lo + i + 2) = __nv_bfloat162(l[2], l[3]);
}

// ---------------- shared HMMA mainloop (128x64, BK=64, split-bf16) ---------
__device__ __forceinline__ void hmma_issue(
    uint32_t sb, int buf,
    const __nv_bfloat16* __restrict__ Ah, const __nv_bfloat16* __restrict__ Al,
    const __nv_bfloat16* __restrict__ Bh, const __nv_bfloat16* __restrict__ Bl,
    int row0, int col0, int kc)
{
    int tid = threadIdx.x;
    uint32_t bb = sb + buf * BUF_BYTES;
    // A tiles: 128 rows x 8 segs = 1024 slots
    #pragma unroll
    for (int j = 0; j < 4; j++) {
        int idx = tid + j * 256;
        int row = idx >> 3, seg = idx & 7;
        uint32_t so = row * ROWB + seg * 16;
        const size_t go = (size_t)(row0 + row) * D + kc + seg * 8;
        cp16(bb + GA_H + so, Ah + go);
        cp16(bb + GA_L + so, Al + go);
    }
    // B tiles: 64 rows x 8 segs = 512 slots
    #pragma unroll
    for (int j = 0; j < 2; j++) {
        int idx = tid + j * 256;
        int row = idx >> 3, seg = idx & 7;
        uint32_t so = row * ROWB + seg * 16;
        const size_t go = (size_t)(col0 + row) * D + kc + seg * 8;
        cp16(bb + GB_H + so, Bh + go);
        cp16(bb + GB_L + so, Bl + go);
    }
}

__device__ __forceinline__ void hmma_gemm(
    uint32_t sb,
    const __nv_bfloat16* __restrict__ Ah, const __nv_bfloat16* __restrict__ Al,
    const __nv_bfloat16* __restrict__ Bh, const __nv_bfloat16* __restrict__ Bl,
    int row0, int col0, float c[2][4][4])
{
    int tid = threadIdx.x;
    int lane = tid & 31, wid = tid >> 5;
    int m0 = (wid >> 1) * 32, n0 = (wid & 1) * 32;
    int mt = lane >> 3, lr = lane & 7;
    uint32_t aoff = (uint32_t)((m0 + (mt & 1) * 8 + lr) * ROWB + ((mt >> 1) * 8) * 2);
    uint32_t boff = (uint32_t)((n0 + (mt >> 1) * 8 + lr) * ROWB + ((mt & 1) * 8) * 2);

    #pragma unroll
    for (int i = 0; i < 2; i++)
        #pragma unroll
        for (int j = 0; j < 4; j++)
            #pragma unroll
            for (int f = 0; f < 4; f++) c[i][j][f] = 0.f;

    hmma_issue(sb, 0, Ah, Al, Bh, Bl, row0, col0, 0);  cp_commit();
    hmma_issue(sb, 1, Ah, Al, Bh, Bl, row0, col0, BK); cp_commit();

    #pragma unroll 1
    for (int cch = 0; cch < NCHUNK; cch++) {
        if (cch < NCHUNK - 1) cp_wait<1>(); else cp_wait<0>();
        __syncthreads();
        uint32_t bufb = sb + (cch & 1) * BUF_BYTES;

        #pragma unroll
        for (int kk = 0; kk < BK; kk += 16) {
            uint32_t bh[4][2], bl[4][2];
            #pragma unroll
            for (int jp = 0; jp < 2; jp++) {
                uint32_t r[4];
                ldsm4(r, bufb + GB_H + boff + jp * 16 * ROWB + kk * 2);
                bh[2*jp][0] = r[0]; bh[2*jp][1] = r[1];
                bh[2*jp+1][0] = r[2]; bh[2*jp+1][1] = r[3];
                ldsm4(r, bufb + GB_L + boff + jp * 16 * ROWB + kk * 2);
                bl[2*jp][0] = r[0]; bl[2*jp][1] = r[1];
                bl[2*jp+1][0] = r[2]; bl[2*jp+1][1] = r[3];
            }
            #pragma unroll
            for (int i = 0; i < 2; i++) {
                uint32_t ah[4], al[4];
                ldsm4(ah, bufb + GA_H + aoff + i * 16 * ROWB + kk * 2);
                ldsm4(al, bufb + GA_L + aoff + i * 16 * ROWB + kk * 2);
                #pragma unroll
                for (int j = 0; j < 4; j++) {
                    mma16816(c[i][j], ah, bh[j]);
                    mma16816(c[i][j], ah, bl[j]);
                    mma16816(c[i][j], al, bh[j]);
                }
            }
        }
        __syncthreads();
        if (cch + 2 < NCHUNK) { hmma_issue(sb, cch & 1, Ah, Al, Bh, Bl, row0, col0, (cch + 2) * BK); cp_commit(); }
    }
}

// ---------------- projection GEMM: epilogue emits split-bf16 Q/K (+V transposed)
__global__ __launch_bounds__(GTHREADS, 2)
void proj_hmma() {
    extern __shared__ char sm[];
    uint32_t sb = smem_u32(sm);
    const __nv_bfloat16 *Ah, *Al, *Bh, *Bl;
    int z = blockIdx.z;
    if (z == 0)      { Ah = g_qh; Al = g_ql; Bh = g_Wqh; Bl = g_Wql; }
    else if (z == 1) { Ah = g_kh; Al = g_kl; Bh = g_Wkh; Bl = g_Wkl; }
    else             { Ah = g_vh; Al = g_vl; Bh = g_Wvh; Bl = g_Wvl; }
    int row0 = blockIdx.y * BM, col0 = blockIdx.x * BN;

    float c[2][4][4];
    hmma_gemm(sb, Ah, Al, Bh, Bl, row0, col0, c);

    int lane = threadIdx.x & 31, wid = threadIdx.x >> 5;
    int m0 = (wid >> 1) * 32, n0 = (wid & 1) * 32;
    int trow = lane >> 2, tcol = (lane & 3) * 2;
    #pragma unroll
    for (int i = 0; i < 2; i++) {
        #pragma unroll
        for (int half = 0; half < 2; half++) {
            int row = row0 + m0 + 16 * i + trow + half * 8;
            int bb = row >> 11, tt = row & 2047;
            #pragma unroll
            for (int j = 0; j < 4; j++) {
                int col = col0 + n0 + 8 * j + tcol;
                int h = col >> 6, d = col & 63;
                size_t bh_ = (size_t)bb * H + h;
                float v0 = c[i][j][half * 2 + 0];
                float v1 = c[i][j][half * 2 + 1];
                __nv_bfloat16 h0 = __float2bfloat16(v0);
                __nv_bfloat16 h1 = __float2bfloat16(v1);
                __nv_bfloat16 l0 = __float2bfloat16(v0 - __bfloat162float(h0));
                __nv_bfloat16 l1 = __float2bfloat16(v1 - __bfloat162float(h1));
                if (z == 0) {
                    size_t o = (bh_ * T + tt) * HD + d;
                    *(uint32_t*)(g_aQh + o) = pack_hilo(h0, h1);
                    *(uint32_t*)(g_aQl + o) = pack_hilo(l0, l1);
                } else if (z == 1) {
                    size_t o = (bh_ * T + tt) * HD + d;
                    *(uint32_t*)(g_aKh + o) = pack_hilo(h0, h1);
                    *(uint32_t*)(g_aKl + o) = pack_hilo(l0, l1);
                } else {
                    // V transposed: [bh][n][t]
                    size_t o0 = (bh_ * HD + d) * T + tt;
                    size_t o1 = (bh_ * HD + d + 1) * T + tt;
                    g_aVh[o0] = h0; g_aVh[o1] = h1;
                    g_aVl[o0] = l0; g_aVl[o1] = l1;
                }
            }
        }
    }
}

// ---------------- output projection GEMM + bias ----------------
__global__ __launch_bounds__(GTHREADS, 2)
void out_hmma(const float* __restrict__ bo, float* __restrict__ dout) {
    extern __shared__ char sm[];
    uint32_t sb = smem_u32(sm);
    int row0 = blockIdx.y * BM, col0 = blockIdx.x * BN;

    float c[2][4][4];
    hmma_gemm(sb, g_Oh, g_Ol, g_Woh, g_Wol, row0, col0, c);

    int lane = threadIdx.x & 31, wid = threadIdx.x >> 5;
    int m0 = (wid >> 1) * 32, n0 = (wid & 1) * 32;
    int trow = lane >> 2, tcol = (lane & 3) * 2;
    #pragma unroll
    for (int i = 0; i < 2; i++) {
        #pragma unroll
        for (int half = 0; half < 2; half++) {
            int row = row0 + m0 + 16 * i + trow + half * 8;
            #pragma unroll
            for (int j = 0; j < 4; j++) {
                int col = col0 + n0 + 8 * j + tcol;
                float2 b2 = *(const float2*)(bo + col);
                float2 v2 = make_float2(c[i][j][half * 2 + 0] + b2.x,
                                        c[i][j][half * 2 + 1] + b2.y);
                *(float2*)(dout + (size_t)row * D + col) = v2;
            }
        }
    }
}

// ---------------------------------------------------------------------------
// HMMA flash attention: CTA = 128 q-rows, 8 warps x 16 rows, BC=64 keys/chunk
// 2-stage KV pipeline, 2 CTAs/SM
// ---------------------------------------------------------------------------
#define ROWK 144                       // 64 bf16 (128B) + 16B pad
#define AQ_H 0
#define AQ_L 18432
#define KV0  36864
#define KVSTAGE 36864                  // per stage: Kh,Kl,Vh,Vl @ 9216 each
#define AK_H 0
#define AK_L 9216
#define AV_H 18432
#define AV_L 27648
#define ATT_SMEM (KV0 + 2 * KVSTAGE)   // 110592

__device__ __forceinline__ void attn_fill_kv(uint32_t st, int bh, int kc) {
    int tid = threadIdx.x;
    #pragma unroll
    for (int r = 0; r < 2; r++) {
        int idx = tid + r * 256;
        int row = idx >> 3, seg = idx & 7;
        size_t kb = ((size_t)bh * T + kc + row) * HD + seg * 8;
        size_t vb = ((size_t)bh * HD + row) * T + kc + seg * 8;
        uint32_t so = row * ROWK + seg * 16;
        cp16(st + AK_H + so, g_aKh + kb);
        cp16(st + AK_L + so, g_aKl + kb);
        cp16(st + AV_H + so, g_aVh + vb);
        cp16(st + AV_L + so, g_aVl + vb);
    }
}

__global__ __launch_bounds__(256, 2) void attn_hmma()
{
    extern __shared__ char sm[];
    uint32_t sb = smem_u32(sm);
    int bh = blockIdx.y;
    int qt0 = blockIdx.x * 128;
    int tid = threadIdx.x, lane = tid & 31, warp = tid >> 5;
    int mt = lane >> 3, lr = lane & 7, g = lane >> 2, tig = lane & 3;

    // Q tile fill (128 rows x 8 segs, hi+lo) — grouped with KV stage 0
    {
        const __nv_bfloat16* qh = g_aQh + ((size_t)bh * T + qt0) * HD;
        const __nv_bfloat16* ql = g_aQl + ((size_t)bh * T + qt0) * HD;
        #pragma unroll
        for (int r = 0; r < 4; r++) {
            int idx = tid + r * 256;
            int row = idx >> 3, seg = idx & 7;
            cp16(sb + AQ_H + row * ROWK + seg * 16, qh + (size_t)row * HD + seg * 8);
            cp16(sb + AQ_L + row * ROWK + seg * 16, ql + (size_t)row * HD + seg * 8);
        }
    }
    attn_fill_kv(sb + KV0, bh, 0);
    cp_commit();

    float o[8][4];
    #pragma unroll
    for (int j = 0; j < 8; j++)
        #pragma unroll
        for (int f = 0; f < 4; f++) o[j][f] = 0.f;
    float m0 = -1e30f, m1 = -1e30f, l0 = 0.f, l1 = 0.f;

    uint32_t aoffQ = (uint32_t)((warp * 16 + (mt & 1) * 8 + lr) * ROWK + ((mt >> 1) * 8) * 2);
    uint32_t boff  = (uint32_t)(((mt >> 1) * 8 + lr) * ROWK + ((mt & 1) * 8) * 2);

    #pragma unroll 1
    for (int ci = 0; ci < 32; ci++) {
        if (ci + 1 < 32) {
            attn_fill_kv(sb + KV0 + ((ci + 1) & 1) * KVSTAGE, bh, (ci + 1) * 64);
            cp_commit();
            cp_wait<1>();
        } else {
            cp_wait<0>();
        }
        __syncthreads();
        uint32_t st = sb + KV0 + (ci & 1) * KVSTAGE;

        // ---- S = Q K^T (split-bf16, fp32 accum): warp computes 16x64 ----
        float s[8][4];
        #pragma unroll
        for (int j = 0; j < 8; j++)
            #pragma unroll
            for (int f = 0; f < 4; f++) s[j][f] = 0.f;

        #pragma unroll
        for (int kk = 0; kk < 64; kk += 16) {
            uint32_t ah[4], al[4];
            ldsm4(ah, sb + AQ_H + aoffQ + kk * 2);
            ldsm4(al, sb + AQ_L + aoffQ + kk * 2);
            #pragma unroll
            for (int jp = 0; jp < 4; jp++) {
                uint32_t kh[4], kl[4];
                ldsm4(kh, st + AK_H + boff + jp * 16 * ROWK + kk * 2);
                ldsm4(kl, st + AK_L + boff + jp * 16 * ROWK + kk * 2);
                mma16816(s[2*jp],   ah, kh);     mma16816(s[2*jp],   ah, kl);     mma16816(s[2*jp],   al, kh);
                mma16816(s[2*jp+1], ah, kh + 2); mma16816(s[2*jp+1], ah, kl + 2); mma16816(s[2*jp+1], al, kh + 2);
            }
        }

        // ---- online softmax (rows g, g+8 per lane; reduce over 4 lanes/row)
        float mx0 = -1e30f, mx1 = -1e30f;
        #pragma unroll
        for (int j = 0; j < 8; j++) {
            s[j][0] *= 0.125f; s[j][1] *= 0.125f; s[j][2] *= 0.125f; s[j][3] *= 0.125f;
            mx0 = fmaxf(mx0, fmaxf(s[j][0], s[j][1]));
            mx1 = fmaxf(mx1, fmaxf(s[j][2], s[j][3]));
        }
        mx0 = fmaxf(mx0, __shfl_xor_sync(0xffffffffu, mx0, 1));
        mx0 = fmaxf(mx0, __shfl_xor_sync(0xffffffffu, mx0, 2));
        mx1 = fmaxf(mx1, __shfl_xor_sync(0xffffffffu, mx1, 1));
        mx1 = fmaxf(mx1, __shfl_xor_sync(0xffffffffu, mx1, 2));
        float nm0 = fmaxf(m0, mx0), nm1 = fmaxf(m1, mx1);
        float al0 = __expf(m0 - nm0), al1 = __expf(m1 - nm1);
        m0 = nm0; m1 = nm1;
        float rs0 = 0.f, rs1 = 0.f;
        #pragma unroll
        for (int j = 0; j < 8; j++) {
            s[j][0] = __expf(s[j][0] - m0); rs0 += s[j][0];
            s[j][1] = __expf(s[j][1] - m0); rs0 += s[j][1];
            s[j][2] = __expf(s[j][2] - m1); rs1 += s[j][2];
            s[j][3] = __expf(s[j][3] - m1); rs1 += s[j][3];
        }
        rs0 += __shfl_xor_sync(0xffffffffu, rs0, 1);
        rs0 += __shfl_xor_sync(0xffffffffu, rs0, 2);
        rs1 += __shfl_xor_sync(0xffffffffu, rs1, 1);
        rs1 += __shfl_xor_sync(0xffffffffu, rs1, 2);
        l0 = l0 * al0 + rs0;
        l1 = l1 * al1 + rs1;
        #pragma unroll
        for (int j = 0; j < 8; j++) {
            o[j][0] *= al0; o[j][1] *= al0; o[j][2] *= al1; o[j][3] *= al1;
        }

        // ---- O += P V (split P, split V; C-layout == A-layout trick) ----
        #pragma unroll
        for (int j2 = 0; j2 < 4; j2++) {
            uint32_t aPh[4], aPl[4];
            #pragma unroll
            for (int q2 = 0; q2 < 2; q2++) {
                float p0 = s[2*j2+q2][0], p1 = s[2*j2+q2][1];
                float p2 = s[2*j2+q2][2], p3 = s[2*j2+q2][3];
                __nv_bfloat16 h0 = __float2bfloat16(p0), h1 = __float2bfloat16(p1);
                __nv_bfloat16 h2 = __float2bfloat16(p2), h3 = __float2bfloat16(p3);
                aPh[q2*2+0] = pack_hilo(h0, h1);
                aPh[q2*2+1] = pack_hilo(h2, h3);
                aPl[q2*2+0] = pack_hilo(__float2bfloat16(p0 - __bfloat162float(h0)),
                                        __float2bfloat16(p1 - __bfloat162float(h1)));
                aPl[q2*2+1] = pack_hilo(__float2bfloat16(p2 - __bfloat162float(h2)),
                                        __float2bfloat16(p3 - __bfloat162float(h3)));
            }
            #pragma unroll
            for (int dp = 0; dp < 4; dp++) {
                uint32_t vh[4], vl[4];
                ldsm4(vh, st + AV_H + boff + dp * 16 * ROWK + j2 * 32);
                ldsm4(vl, st + AV_L + boff + dp * 16 * ROWK + j2 * 32);
                mma16816(o[2*dp],   aPh, vh);     mma16816(o[2*dp],   aPh, vl);     mma16816(o[2*dp],   aPl, vh);
                mma16816(o[2*dp+1], aPh, vh + 2); mma16816(o[2*dp+1], aPh, vl + 2); mma16816(o[2*dp+1], aPl, vh + 2);
            }
        }
        __syncthreads();
    }

    // ---- epilogue: O/l -> bf16 hi/lo at [b][t][h*64+d] ----
    float inv0 = 1.f / l0, inv1 = 1.f / l1;
    int b = bh >> 4, h = bh & 15;
    int tA = qt0 + warp * 16 + g;
    int tB = tA + 8;
    #pragma unroll
    for (int j = 0; j < 8; j++) {
        int d = h * 64 + 8 * j + 2 * tig;
        {
            float x0 = o[j][0] * inv0, x1 = o[j][1] * inv0;
            __nv_bfloat16 h0 = __float2bfloat16(x0), h1 = __float2bfloat16(x1);
            size_t off = ((size_t)b * T + tA) * D + d;
            *(uint32_t*)(g_Oh + off) = pack_hilo(h0, h1);
            *(uint32_t*)(g_Ol + off) = pack_hilo(__float2bfloat16(x0 - __bfloat162float(h0)),
                                                 __float2bfloat16(x1 - __bfloat162float(h1)));
        }
        {
            float y0 = o[j][2] * inv1, y1 = o[j][3] * inv1;
            __nv_bfloat16 h0 = __float2bfloat16(y0), h1 = __float2bfloat16(y1);
            size_t off = ((size_t)b * T + tB) * D + d;
            *(uint32_t*)(g_Oh + off) = pack_hilo(h0, h1);
            *(uint32_t*)(g_Ol + off) = pack_hilo(__float2bfloat16(y0 - __bfloat162float(h0)),
                                                 __float2bfloat16(y1 - __bfloat162float(h1)));
        }
    }
}

// ---------------------------------------------------------------------------
extern "C" void kernel_launch(void* const* d_in, const int* in_sizes, int n_in,
                              void* d_out, int out_size)
{
    const float* k  = (const float*)d_in[0];
    const float* q  = (const float*)d_in[1];
    const float* v  = (const float*)d_in[2];
    const float* Wk = (const float*)d_in[3];
    const float* Wq = (const float*)d_in[4];
    const float* Wv = (const float*)d_in[5];
    const float* Wo = (const float*)d_in[6];
    const float* bo = (const float*)d_in[7];
    float* out = (float*)d_out;

    cudaFuncSetAttribute(proj_hmma, cudaFuncAttributeMaxDynamicSharedMemorySize, GEMM_SMEM);
    cudaFuncSetAttribute(out_hmma,  cudaFuncAttributeMaxDynamicSharedMemorySize, GEMM_SMEM);
    cudaFuncSetAttribute(attn_hmma, cudaFuncAttributeMaxDynamicSharedMemorySize, ATT_SMEM);

    // 1) split inputs/weights into bf16 hi/lo
    cvt_all<<<16384, 256>>>(q, k, v, Wq, Wk, Wv, Wo);

    // 2) Q/K/V projections (tensor cores); epilogue emits split-bf16 Q/K + V^T
    proj_hmma<<<dim3(D/BN, (BATCH*T)/BM, 3), GTHREADS, GEMM_SMEM>>>();

    // 3) flash attention on tensor cores (split-bf16 S and PV), 2 CTAs/SM
    attn_hmma<<<dim3(T/128, BATCH*H), 256, ATT_SMEM>>>();

    // 4) output projection + bias (tensor cores)
    out_hmma<<<dim3(D/BN, (BATCH*T)/BM), GTHREADS, GEMM_SMEM>>>(bo, out);
}

// round 16
// speedup vs baseline: 3.8631x; 1.0023x over previous
#include <cuda_runtime.h>
#include <cuda_bf16.h>
#include <cstdint>

#define BATCH 2
#define T 2048
#define D 1024
#define H 16
#define HD 64

// ---------------- scratch (allocation-free) ----------------
__device__ __nv_bfloat16 g_qh[BATCH*T*D], g_ql[BATCH*T*D];
__device__ __nv_bfloat16 g_kh[BATCH*T*D], g_kl[BATCH*T*D];
__device__ __nv_bfloat16 g_vh[BATCH*T*D], g_vl[BATCH*T*D];
__device__ __nv_bfloat16 g_Wqh[D*D], g_Wql[D*D];
__device__ __nv_bfloat16 g_Wkh[D*D], g_Wkl[D*D];
__device__ __nv_bfloat16 g_Wvh[D*D], g_Wvl[D*D];
__device__ __nv_bfloat16 g_Woh[D*D], g_Wol[D*D];
// projected Q/K (split, [bh][t][n]) and V (split, TRANSPOSED [bh][n][t])
__device__ __nv_bfloat16 g_aQh[BATCH*H*T*HD], g_aQl[BATCH*H*T*HD];
__device__ __nv_bfloat16 g_aKh[BATCH*H*T*HD], g_aKl[BATCH*H*T*HD];
__device__ __nv_bfloat16 g_aVh[BATCH*H*T*HD], g_aVl[BATCH*H*T*HD];
// attention output (split, [b][t][h*64+d])
__device__ __nv_bfloat16 g_Oh[BATCH*T*D], g_Ol[BATCH*T*D];

// ---------------- PTX helpers (family-portable: sm_80+ only) ----------------
__device__ __forceinline__ uint32_t smem_u32(const void* p) {
    uint32_t a;
    asm("{ .reg .u64 t; cvta.to.shared.u64 t, %1; cvt.u32.u64 %0, t; }" : "=r"(a) : "l"(p));
    return a;
}
__device__ __forceinline__ void cp16(uint32_t s, const void* g) {
    asm volatile("cp.async.cg.shared.global [%0], [%1], 16;" :: "r"(s), "l"(g));
}
__device__ __forceinline__ void cp_commit() {
    asm volatile("cp.async.commit_group;" ::: "memory");
}
template<int N> __device__ __forceinline__ void cp_wait() {
    asm volatile("cp.async.wait_group %0;" :: "n"(N) : "memory");
}
__device__ __forceinline__ void ldsm4(uint32_t* r, uint32_t addr) {
    asm volatile("ldmatrix.sync.aligned.m8n8.x4.shared.b16 {%0,%1,%2,%3}, [%4];"
                 : "=r"(r[0]), "=r"(r[1]), "=r"(r[2]), "=r"(r[3]) : "r"(addr));
}
__device__ __forceinline__ void mma16816(float* c, const uint32_t* a, const uint32_t* b) {
    asm volatile(
        "mma.sync.aligned.m16n8k16.row.col.f32.bf16.bf16.f32 "
        "{%0,%1,%2,%3}, {%4,%5,%6,%7}, {%8,%9}, {%0,%1,%2,%3};"
        : "+f"(c[0]), "+f"(c[1]), "+f"(c[2]), "+f"(c[3])
        : "r"(a[0]), "r"(a[1]), "r"(a[2]), "r"(a[3]), "r"(b[0]), "r"(b[1]));
}
__device__ __forceinline__ uint32_t pack_hilo(__nv_bfloat16 lo, __nv_bfloat16 hi) {
    __nv_bfloat162 t(lo, hi);
    return *(uint32_t*)&t;
}

// ---------------- GEMM geometry (BM=128, BN=64, BK=64, 2 CTAs/SM) ----------
#define BM 128
#define BN 64
#define BK 64
#define ROWB 144                    // 64 bf16 (128B) + 16B pad; conflict-free ldmatrix
#define A_TILE (128 * ROWB)         // 18432
#define B_TILE (64 * ROWB)          // 9216
#define GA_H 0
#define GA_L A_TILE
#define GB_H (2 * A_TILE)
#define GB_L (2 * A_TILE + B_TILE)
#define BUF_BYTES (2 * A_TILE + 2 * B_TILE)   // 55296
#define GEMM_SMEM (2 * BUF_BYTES)             // 110592
#define GTHREADS 256
#define NCHUNK (D / BK)             // 16

// ---------------- fused split convert: fp32 -> (hi, lo) bf16 ----------------
__global__ __launch_bounds__(256) void cvt_all(
    const float* __restrict__ q, const float* __restrict__ k, const float* __restrict__ v,
    const float* __restrict__ Wq, const float* __restrict__ Wk,
    const float* __restrict__ Wv, const float* __restrict__ Wo)
{
    int b = blockIdx.x;
    const float* src; __nv_bfloat16 *hi, *lo; int lb;
    if (b < 4096)       { src = q;  hi = g_qh;  lo = g_ql;  lb = b; }
    else if (b < 8192)  { src = k;  hi = g_kh;  lo = g_kl;  lb = b - 4096; }
    else if (b < 12288) { src = v;  hi = g_vh;  lo = g_vl;  lb = b - 8192; }
    else if (b < 13312) { src = Wq; hi = g_Wqh; lo = g_Wql; lb = b - 12288; }
    else if (b < 14336) { src = Wk; hi = g_Wkh; lo = g_Wkl; lb = b - 13312; }
    else if (b < 15360) { src = Wv; hi = g_Wvh; lo = g_Wvl; lb = b - 14336; }
    else                { src = Wo; hi = g_Woh; lo = g_Wol; lb = b - 15360; }
    int i = lb * 1024 + threadIdx.x * 4;
    float4 vv4 = *(const float4*)(src + i);
    float vv[4] = {vv4.x, vv4.y, vv4.z, vv4.w};
    __nv_bfloat16 h[4], l[4];
    #pragma unroll
    for (int j = 0; j < 4; j++) {
        h[j] = __float2bfloat16(vv[j]);
        l[j] = __float2bfloat16(vv[j] - __bfloat162float(h[j]));
    }
    *(__nv_bfloat162*)(hi + i)     = __nv_bfloat162(h[0], h[1]);
    *(__nv_bfloat162*)(hi + i + 2) = __nv_bfloat162(h[2], h[3]);
    *(__nv_bfloat162*)(lo + i)     = __nv_bfloat162(l[0], l[1]);
    *(__nv_bfloat162*)(lo + i + 2) = __nv_bfloat162(l[2], l[3]);
}

// ---------------- shared HMMA mainloop (128x64, BK=64, split-bf16) ---------
__device__ __forceinline__ void hmma_issue(
    uint32_t sb, int buf,
    const __nv_bfloat16* __restrict__ Ah, const __nv_bfloat16* __restrict__ Al,
    const __nv_bfloat16* __restrict__ Bh, const __nv_bfloat16* __restrict__ Bl,
    int row0, int col0, int kc)
{
    int tid = threadIdx.x;
    uint32_t bb = sb + buf * BUF_BYTES;
    // A tiles: 128 rows x 8 segs = 1024 slots
    #pragma unroll
    for (int j = 0; j < 4; j++) {
        int idx = tid + j * 256;
        int row = idx >> 3, seg = idx & 7;
        uint32_t so = row * ROWB + seg * 16;
        const size_t go = (size_t)(row0 + row) * D + kc + seg * 8;
        cp16(bb + GA_H + so, Ah + go);
        cp16(bb + GA_L + so, Al + go);
    }
    // B tiles: 64 rows x 8 segs = 512 slots
    #pragma unroll
    for (int j = 0; j < 2; j++) {
        int idx = tid + j * 256;
        int row = idx >> 3, seg = idx & 7;
        uint32_t so = row * ROWB + seg * 16;
        const size_t go = (size_t)(col0 + row) * D + kc + seg * 8;
        cp16(bb + GB_H + so, Bh + go);
        cp16(bb + GB_L + so, Bl + go);
    }
}

__device__ __forceinline__ void hmma_gemm(
    uint32_t sb,
    const __nv_bfloat16* __restrict__ Ah, const __nv_bfloat16* __restrict__ Al,
    const __nv_bfloat16* __restrict__ Bh, const __nv_bfloat16* __restrict__ Bl,
    int row0, int col0, float c[2][4][4])
{
    int tid = threadIdx.x;
    int lane = tid & 31, wid = tid >> 5;
    int m0 = (wid >> 1) * 32, n0 = (wid & 1) * 32;
    int mt = lane >> 3, lr = lane & 7;
    uint32_t aoff = (uint32_t)((m0 + (mt & 1) * 8 + lr) * ROWB + ((mt >> 1) * 8) * 2);
    uint32_t boff = (uint32_t)((n0 + (mt >> 1) * 8 + lr) * ROWB + ((mt & 1) * 8) * 2);

    #pragma unroll
    for (int i = 0; i < 2; i++)
        #pragma unroll
        for (int j = 0; j < 4; j++)
            #pragma unroll
            for (int f = 0; f < 4; f++) c[i][j][f] = 0.f;

    hmma_issue(sb, 0, Ah, Al, Bh, Bl, row0, col0, 0);  cp_commit();
    hmma_issue(sb, 1, Ah, Al, Bh, Bl, row0, col0, BK); cp_commit();

    #pragma unroll 1
    for (int cch = 0; cch < NCHUNK; cch++) {
        if (cch < NCHUNK - 1) cp_wait<1>(); else cp_wait<0>();
        __syncthreads();
        uint32_t bufb = sb + (cch & 1) * BUF_BYTES;

        #pragma unroll
        for (int kk = 0; kk < BK; kk += 16) {
            uint32_t bh[4][2], bl[4][2];
            #pragma unroll
            for (int jp = 0; jp < 2; jp++) {
                uint32_t r[4];
                ldsm4(r, bufb + GB_H + boff + jp * 16 * ROWB + kk * 2);
                bh[2*jp][0] = r[0]; bh[2*jp][1] = r[1];
                bh[2*jp+1][0] = r[2]; bh[2*jp+1][1] = r[3];
                ldsm4(r, bufb + GB_L + boff + jp * 16 * ROWB + kk * 2);
                bl[2*jp][0] = r[0]; bl[2*jp][1] = r[1];
                bl[2*jp+1][0] = r[2]; bl[2*jp+1][1] = r[3];
            }
            #pragma unroll
            for (int i = 0; i < 2; i++) {
                uint32_t ah[4], al[4];
                ldsm4(ah, bufb + GA_H + aoff + i * 16 * ROWB + kk * 2);
                ldsm4(al, bufb + GA_L + aoff + i * 16 * ROWB + kk * 2);
                // term-major: consecutive MMAs hit different accumulators
                // (per-accumulator order stays hh, hl, lh -> bit-identical result)
                #pragma unroll
                for (int j = 0; j < 4; j++) mma16816(c[i][j], ah, bh[j]);
                #pragma unroll
                for (int j = 0; j < 4; j++) mma16816(c[i][j], ah, bl[j]);
                #pragma unroll
                for (int j = 0; j < 4; j++) mma16816(c[i][j], al, bh[j]);
            }
        }
        __syncthreads();
        if (cch + 2 < NCHUNK) { hmma_issue(sb, cch & 1, Ah, Al, Bh, Bl, row0, col0, (cch + 2) * BK); cp_commit(); }
    }
}

// ---------------- projection GEMM: epilogue emits split-bf16 Q/K (+V transposed)
__global__ __launch_bounds__(GTHREADS, 2)
void proj_hmma() {
    extern __shared__ char sm[];
    uint32_t sb = smem_u32(sm);
    const __nv_bfloat16 *Ah, *Al, *Bh, *Bl;
    int z = blockIdx.z;
    if (z == 0)      { Ah = g_qh; Al = g_ql; Bh = g_Wqh; Bl = g_Wql; }
    else if (z == 1) { Ah = g_kh; Al = g_kl; Bh = g_Wkh; Bl = g_Wkl; }
    else             { Ah = g_vh; Al = g_vl; Bh = g_Wvh; Bl = g_Wvl; }
    int row0 = blockIdx.y * BM, col0 = blockIdx.x * BN;

    float c[2][4][4];
    hmma_gemm(sb, Ah, Al, Bh, Bl, row0, col0, c);

    int lane = threadIdx.x & 31, wid = threadIdx.x >> 5;
    int m0 = (wid >> 1) * 32, n0 = (wid & 1) * 32;
    int trow = lane >> 2, tcol = (lane & 3) * 2;
    #pragma unroll
    for (int i = 0; i < 2; i++) {
        #pragma unroll
        for (int half = 0; half < 2; half++) {
            int row = row0 + m0 + 16 * i + trow + half * 8;
            int bb = row >> 11, tt = row & 2047;
            #pragma unroll
            for (int j = 0; j < 4; j++) {
                int col = col0 + n0 + 8 * j + tcol;
                int h = col >> 6, d = col & 63;
                size_t bh_ = (size_t)bb * H + h;
                float v0 = c[i][j][half * 2 + 0];
                float v1 = c[i][j][half * 2 + 1];
                __nv_bfloat16 h0 = __float2bfloat16(v0);
                __nv_bfloat16 h1 = __float2bfloat16(v1);
                __nv_bfloat16 l0 = __float2bfloat16(v0 - __bfloat162float(h0));
                __nv_bfloat16 l1 = __float2bfloat16(v1 - __bfloat162float(h1));
                if (z == 0) {
                    size_t o = (bh_ * T + tt) * HD + d;
                    *(uint32_t*)(g_aQh + o) = pack_hilo(h0, h1);
                    *(uint32_t*)(g_aQl + o) = pack_hilo(l0, l1);
                } else if (z == 1) {
                    size_t o = (bh_ * T + tt) * HD + d;
                    *(uint32_t*)(g_aKh + o) = pack_hilo(h0, h1);
                    *(uint32_t*)(g_aKl + o) = pack_hilo(l0, l1);
                } else {
                    // V transposed: [bh][n][t]
                    size_t o0 = (bh_ * HD + d) * T + tt;
                    size_t o1 = (bh_ * HD + d + 1) * T + tt;
                    g_aVh[o0] = h0; g_aVh[o1] = h1;
                    g_aVl[o0] = l0; g_aVl[o1] = l1;
                }
            }
        }
    }
}

// ---------------- output projection GEMM + bias ----------------
__global__ __launch_bounds__(GTHREADS, 2)
void out_hmma(const float* __restrict__ bo, float* __restrict__ dout) {
    extern __shared__ char sm[];
    uint32_t sb = smem_u32(sm);
    int row0 = blockIdx.y * BM, col0 = blockIdx.x * BN;

    float c[2][4][4];
    hmma_gemm(sb, g_Oh, g_Ol, g_Woh, g_Wol, row0, col0, c);

    int lane = threadIdx.x & 31, wid = threadIdx.x >> 5;
    int m0 = (wid >> 1) * 32, n0 = (wid & 1) * 32;
    int trow = lane >> 2, tcol = (lane & 3) * 2;
    #pragma unroll
    for (int i = 0; i < 2; i++) {
        #pragma unroll
        for (int half = 0; half < 2; half++) {
            int row = row0 + m0 + 16 * i + trow + half * 8;
            #pragma unroll
            for (int j = 0; j < 4; j++) {
                int col = col0 + n0 + 8 * j + tcol;
                float2 b2 = *(const float2*)(bo + col);
                float2 v2 = make_float2(c[i][j][half * 2 + 0] + b2.x,
                                        c[i][j][half * 2 + 1] + b2.y);
                *(float2*)(dout + (size_t)row * D + col) = v2;
            }
        }
    }
}

// ---------------------------------------------------------------------------
// HMMA flash attention: CTA = 128 q-rows, 8 warps x 16 rows, BC=64 keys/chunk
// 2-stage KV pipeline, 2 CTAs/SM; term-major MMA issue (distance-4 chains)
// ---------------------------------------------------------------------------
#define ROWK 144                       // 64 bf16 (128B) + 16B pad
#define AQ_H 0
#define AQ_L 18432
#define KV0  36864
#define KVSTAGE 36864                  // per stage: Kh,Kl,Vh,Vl @ 9216 each
#define AK_H 0
#define AK_L 9216
#define AV_H 18432
#define AV_L 27648
#define ATT_SMEM (KV0 + 2 * KVSTAGE)   // 110592

__device__ __forceinline__ void attn_fill_kv(uint32_t st, int bh, int kc) {
    int tid = threadIdx.x;
    #pragma unroll
    for (int r = 0; r < 2; r++) {
        int idx = tid + r * 256;
        int row = idx >> 3, seg = idx & 7;
        size_t kb = ((size_t)bh * T + kc + row) * HD + seg * 8;
        size_t vb = ((size_t)bh * HD + row) * T + kc + seg * 8;
        uint32_t so = row * ROWK + seg * 16;
        cp16(st + AK_H + so, g_aKh + kb);
        cp16(st + AK_L + so, g_aKl + kb);
        cp16(st + AV_H + so, g_aVh + vb);
        cp16(st + AV_L + so, g_aVl + vb);
    }
}

__global__ __launch_bounds__(256, 2) void attn_hmma()
{
    extern __shared__ char sm[];
    uint32_t sb = smem_u32(sm);
    int bh = blockIdx.y;
    int qt0 = blockIdx.x * 128;
    int tid = threadIdx.x, lane = tid & 31, warp = tid >> 5;
    int mt = lane >> 3, lr = lane & 7, g = lane >> 2, tig = lane & 3;

    // Q tile fill (128 rows x 8 segs, hi+lo) — grouped with KV stage 0
    {
        const __nv_bfloat16* qh = g_aQh + ((size_t)bh * T + qt0) * HD;
        const __nv_bfloat16* ql = g_aQl + ((size_t)bh * T + qt0) * HD;
        #pragma unroll
        for (int r = 0; r < 4; r++) {
            int idx = tid + r * 256;
            int row = idx >> 3, seg = idx & 7;
            cp16(sb + AQ_H + row * ROWK + seg * 16, qh + (size_t)row * HD + seg * 8);
            cp16(sb + AQ_L + row * ROWK + seg * 16, ql + (size_t)row * HD + seg * 8);
        }
    }
    attn_fill_kv(sb + KV0, bh, 0);
    cp_commit();

    float o[8][4];
    #pragma unroll
    for (int j = 0; j < 8; j++)
        #pragma unroll
        for (int f = 0; f < 4; f++) o[j][f] = 0.f;
    float m0 = -1e30f, m1 = -1e30f, l0 = 0.f, l1 = 0.f;

    uint32_t aoffQ = (uint32_t)((warp * 16 + (mt & 1) * 8 + lr) * ROWK + ((mt >> 1) * 8) * 2);
    uint32_t boff  = (uint32_t)(((mt >> 1) * 8 + lr) * ROWK + ((mt & 1) * 8) * 2);

    #pragma unroll 1
    for (int ci = 0; ci < 32; ci++) {
        if (ci + 1 < 32) {
            attn_fill_kv(sb + KV0 + ((ci + 1) & 1) * KVSTAGE, bh, (ci + 1) * 64);
            cp_commit();
            cp_wait<1>();
        } else {
            cp_wait<0>();
        }
        __syncthreads();
        uint32_t st = sb + KV0 + (ci & 1) * KVSTAGE;

        // ---- S = Q K^T (split-bf16, fp32 accum): warp computes 16x64 ----
        float s[8][4];
        #pragma unroll
        for (int j = 0; j < 8; j++)
            #pragma unroll
            for (int f = 0; f < 4; f++) s[j][f] = 0.f;

        #pragma unroll
        for (int kk = 0; kk < 64; kk += 16) {
            uint32_t ah[4], al[4];
            ldsm4(ah, sb + AQ_H + aoffQ + kk * 2);
            ldsm4(al, sb + AQ_L + aoffQ + kk * 2);
            #pragma unroll
            for (int jp2 = 0; jp2 < 2; jp2++) {
                uint32_t kh0[4], kl0[4], kh1[4], kl1[4];
                ldsm4(kh0, st + AK_H + boff + (2*jp2+0) * 16 * ROWK + kk * 2);
                ldsm4(kl0, st + AK_L + boff + (2*jp2+0) * 16 * ROWK + kk * 2);
                ldsm4(kh1, st + AK_H + boff + (2*jp2+1) * 16 * ROWK + kk * 2);
                ldsm4(kl1, st + AK_L + boff + (2*jp2+1) * 16 * ROWK + kk * 2);
                float* s0 = s[4*jp2+0]; float* s1 = s[4*jp2+1];
                float* s2 = s[4*jp2+2]; float* s3 = s[4*jp2+3];
                // term-major, distance-4 accumulator reuse
                mma16816(s0, ah, kh0); mma16816(s1, ah, kh0 + 2);
                mma16816(s2, ah, kh1); mma16816(s3, ah, kh1 + 2);
                mma16816(s0, ah, kl0); mma16816(s1, ah, kl0 + 2);
                mma16816(s2, ah, kl1); mma16816(s3, ah, kl1 + 2);
                mma16816(s0, al, kh0); mma16816(s1, al, kh0 + 2);
                mma16816(s2, al, kh1); mma16816(s3, al, kh1 + 2);
            }
        }

        // ---- online softmax (rows g, g+8 per lane; reduce over 4 lanes/row)
        float mx0 = -1e30f, mx1 = -1e30f;
        #pragma unroll
        for (int j = 0; j < 8; j++) {
            s[j][0] *= 0.125f; s[j][1] *= 0.125f; s[j][2] *= 0.125f; s[j][3] *= 0.125f;
            mx0 = fmaxf(mx0, fmaxf(s[j][0], s[j][1]));
            mx1 = fmaxf(mx1, fmaxf(s[j][2], s[j][3]));
        }
        mx0 = fmaxf(mx0, __shfl_xor_sync(0xffffffffu, mx0, 1));
        mx0 = fmaxf(mx0, __shfl_xor_sync(0xffffffffu, mx0, 2));
        mx1 = fmaxf(mx1, __shfl_xor_sync(0xffffffffu, mx1, 1));
        mx1 = fmaxf(mx1, __shfl_xor_sync(0xffffffffu, mx1, 2));
        float nm0 = fmaxf(m0, mx0), nm1 = fmaxf(m1, mx1);
        float al0 = __expf(m0 - nm0), al1 = __expf(m1 - nm1);
        m0 = nm0; m1 = nm1;
        float rs0 = 0.f, rs1 = 0.f;
        #pragma unroll
        for (int j = 0; j < 8; j++) {
            s[j][0] = __expf(s[j][0] - m0); rs0 += s[j][0];
            s[j][1] = __expf(s[j][1] - m0); rs0 += s[j][1];
            s[j][2] = __expf(s[j][2] - m1); rs1 += s[j][2];
            s[j][3] = __expf(s[j][3] - m1); rs1 += s[j][3];
        }
        rs0 += __shfl_xor_sync(0xffffffffu, rs0, 1);
        rs0 += __shfl_xor_sync(0xffffffffu, rs0, 2);
        rs1 += __shfl_xor_sync(0xffffffffu, rs1, 1);
        rs1 += __shfl_xor_sync(0xffffffffu, rs1, 2);
        l0 = l0 * al0 + rs0;
        l1 = l1 * al1 + rs1;
        #pragma unroll
        for (int j = 0; j < 8; j++) {
            o[j][0] *= al0; o[j][1] *= al0; o[j][2] *= al1; o[j][3] *= al1;
        }

        // ---- O += P V (split P, split V; C-layout == A-layout trick) ----
        #pragma unroll
        for (int j2 = 0; j2 < 4; j2++) {
            uint32_t aPh[4], aPl[4];
            #pragma unroll
            for (int q2 = 0; q2 < 2; q2++) {
                float p0 = s[2*j2+q2][0], p1 = s[2*j2+q2][1];
                float p2 = s[2*j2+q2][2], p3 = s[2*j2+q2][3];
                __nv_bfloat16 h0 = __float2bfloat16(p0), h1 = __float2bfloat16(p1);
                __nv_bfloat16 h2 = __float2bfloat16(p2), h3 = __float2bfloat16(p3);
                aPh[q2*2+0] = pack_hilo(h0, h1);
                aPh[q2*2+1] = pack_hilo(h2, h3);
                aPl[q2*2+0] = pack_hilo(__float2bfloat16(p0 - __bfloat162float(h0)),
                                        __float2bfloat16(p1 - __bfloat162float(h1)));
                aPl[q2*2+1] = pack_hilo(__float2bfloat16(p2 - __bfloat162float(h2)),
                                        __float2bfloat16(p3 - __bfloat162float(h3)));
            }
            #pragma unroll
            for (int dp2 = 0; dp2 < 2; dp2++) {
                uint32_t vh0[4], vl0[4], vh1[4], vl1[4];
                ldsm4(vh0, st + AV_H + boff + (2*dp2+0) * 16 * ROWK + j2 * 32);
                ldsm4(vl0, st + AV_L + boff + (2*dp2+0) * 16 * ROWK + j2 * 32);
                ldsm4(vh1, st + AV_H + boff + (2*dp2+1) * 16 * ROWK + j2 * 32);
                ldsm4(vl1, st + AV_L + boff + (2*dp2+1) * 16 * ROWK + j2 * 32);
                float* o0 = o[4*dp2+0]; float* o1 = o[4*dp2+1];
                float* o2 = o[4*dp2+2]; float* o3 = o[4*dp2+3];
                // term-major, distance-4 accumulator reuse
                mma16816(o0, aPh, vh0); mma16816(o1, aPh, vh0 + 2);
                mma16816(o2, aPh, vh1); mma16816(o3, aPh, vh1 + 2);
                mma16816(o0, aPh, vl0); mma16816(o1, aPh, vl0 + 2);
                mma16816(o2, aPh, vl1); mma16816(o3, aPh, vl1 + 2);
                mma16816(o0, aPl, vh0); mma16816(o1, aPl, vh0 + 2);
                mma16816(o2, aPl, vh1); mma16816(o3, aPl, vh1 + 2);
            }
        }
        __syncthreads();
    }

    // ---- epilogue: O/l -> bf16 hi/lo at [b][t][h*64+d] ----
    float inv0 = 1.f / l0, inv1 = 1.f / l1;
    int b = bh >> 4, h = bh & 15;
    int tA = qt0 + warp * 16 + g;
    int tB = tA + 8;
    #pragma unroll
    for (int j = 0; j < 8; j++) {
        int d = h * 64 + 8 * j + 2 * tig;
        {
            float x0 = o[j][0] * inv0, x1 = o[j][1] * inv0;
            __nv_bfloat16 h0 = __float2bfloat16(x0), h1 = __float2bfloat16(x1);
            size_t off = ((size_t)b * T + tA) * D + d;
            *(uint32_t*)(g_Oh + off) = pack_hilo(h0, h1);
            *(uint32_t*)(g_Ol + off) = pack_hilo(__float2bfloat16(x0 - __bfloat162float(h0)),
                                                 __float2bfloat16(x1 - __bfloat162float(h1)));
        }
        {
            float y0 = o[j][2] * inv1, y1 = o[j][3] * inv1;
            __nv_bfloat16 h0 = __float2bfloat16(y0), h1 = __float2bfloat16(y1);
            size_t off = ((size_t)b * T + tB) * D + d;
            *(uint32_t*)(g_Oh + off) = pack_hilo(h0, h1);
            *(uint32_t*)(g_Ol + off) = pack_hilo(__float2bfloat16(y0 - __bfloat162float(h0)),
                                                 __float2bfloat16(y1 - __bfloat162float(h1)));
        }
    }
}

// ---------------------------------------------------------------------------
extern "C" void kernel_launch(void* const* d_in, const int* in_sizes, int n_in,
                              void* d_out, int out_size)
{
    const float* k  = (const float*)d_in[0];
    const float* q  = (const float*)d_in[1];
    const float* v  = (const float*)d_in[2];
    const float* Wk = (const float*)d_in[3];
    const float* Wq = (const float*)d_in[4];
    const float* Wv = (const float*)d_in[5];
    const float* Wo = (const float*)d_in[6];
    const float* bo = (const float*)d_in[7];
    float* out = (float*)d_out;

    cudaFuncSetAttribute(proj_hmma, cudaFuncAttributeMaxDynamicSharedMemorySize, GEMM_SMEM);
    cudaFuncSetAttribute(out_hmma,  cudaFuncAttributeMaxDynamicSharedMemorySize, GEMM_SMEM);
    cudaFuncSetAttribute(attn_hmma, cudaFuncAttributeMaxDynamicSharedMemorySize, ATT_SMEM);

    // 1) split inputs/weights into bf16 hi/lo
    cvt_all<<<16384, 256>>>(q, k, v, Wq, Wk, Wv, Wo);

    // 2) Q/K/V projections (tensor cores); epilogue emits split-bf16 Q/K + V^T
    proj_hmma<<<dim3(D/BN, (BATCH*T)/BM, 3), GTHREADS, GEMM_SMEM>>>();

    // 3) flash attention on tensor cores (split-bf16 S and PV), 2 CTAs/SM
    attn_hmma<<<dim3(T/128, BATCH*H), 256, ATT_SMEM>>>();

    // 4) output projection + bias (tensor cores)
    out_hmma<<<dim3(D/BN, (BATCH*T)/BM), GTHREADS, GEMM_SMEM>>>(bo, out);
}